// round 10
// baseline (speedup 1.0000x reference)
#include <cuda_runtime.h>
#include <math.h>
#include <stdint.h>

#define BB      2
#define FRAMES  4
#define LSEQ    784
#define NT      1568
#define DM      256
#define DI      512
#define DSTATE  16
#define DTR     16
#define NDEPTH  12
#define NPATCH  196
#define KPATCH  768
#define NCHUNK  7
#define CLEN    112
#define NGRP    (2 * BB * DI * DSTATE)
#define NCHAIN  128   // 2 dirs * 64 bx

// ---------------- scratch ----------------
__device__ float g_im2col[NT * KPATCH];
__device__ float g_hidden[NT * DM];
__device__ float g_resid [NT * DM];
__device__ float g_hnorm [NT * DM];
__device__ float g_xz    [NT * 2 * DI];
__device__ float g_xs    [2 * DI * NT];   // TRANSPOSED: [dir][d][b*784+t]
__device__ float g_gz    [DI * NT];       // TRANSPOSED silu(z)
__device__ float g_dbl   [2 * NT * 48];
__device__ float g_dt    [2 * DI * NT];   // TRANSPOSED
__device__ float g_y     [2 * DI * NT];   // TRANSPOSED
__device__ float g_A     [2 * NDEPTH * DI * DSTATE];
__device__ float g_fus   [BB * 5 * DM];
__device__ float g_hbuf  [NGRP];          // chunk-exit states
__device__ int   g_ticket[NCHAIN];
__device__ int   g_done  [NCHAIN];

static __device__ __forceinline__ float siluf(float x) {
    return x / (1.f + __expf(-x));
}
static __device__ __forceinline__ float softplusf(float x) {
    return (x > 20.f) ? x : log1pf(__expf(x));
}
static __device__ __forceinline__ uint32_t f2tf32(float x) {
    uint32_t r;
    asm("cvt.rna.tf32.f32 %0, %1;" : "=r"(r) : "f"(x));
    return r;
}
static __device__ __forceinline__ void mma_tf32(float* d, const uint32_t* a, const uint32_t* b) {
    asm volatile(
        "mma.sync.aligned.m16n8k8.row.col.f32.tf32.tf32.f32 "
        "{%0,%1,%2,%3}, {%4,%5,%6,%7}, {%8,%9}, {%0,%1,%2,%3};"
        : "+f"(d[0]), "+f"(d[1]), "+f"(d[2]), "+f"(d[3])
        : "r"(a[0]), "r"(a[1]), "r"(a[2]), "r"(a[3]), "r"(b[0]), "r"(b[1]));
}

__global__ void prep_A_kernel(const float* __restrict__ Af, const float* __restrict__ Ab) {
    int e = blockIdx.x * blockDim.x + threadIdx.x;
    const int N = NDEPTH * DI * DSTATE;
    if (e < N) {
        g_A[e]     = -expf(Af[e]);
        g_A[N + e] = -expf(Ab[e]);
    }
}

__global__ void im2col_kernel(const float* __restrict__ x) {
    int e = blockIdx.x * blockDim.x + threadIdx.x;
    if (e >= NT * KPATCH) return;
    if (e < NT * DM) g_hidden[e] = 0.f;
    int n = e / KPATCH, k = e % KPATCH;
    int b = n / LSEQ, tl = n % LSEQ;
    int t = tl / NPATCH, p = tl % NPATCH;
    int ph = p / 14, pw = p % 14;
    int ci = k / 256, rem = k % 256;
    int ii = rem / 16, jj = rem % 16;
    long off = (((long)(b * 3 + ci) * FRAMES + t) * 224 + (ph * 16 + ii)) * 224 + (pw * 16 + jj);
    g_im2col[e] = x[off];
}

// ---------------- TF32 tensor-core GEMM, 64x64 tile, 4 warps ------------------
// C[M,N] = (A [+A2]) @ W^T ; W is N x K row-major. z = dir*SK + ks.
// TRANSA: A col-major A[k*lda + row]. TRANSC: C written transposed, smem-staged.
// EPI: 0 none, 1 softplus(+bias), 2 patch epilogue (ks==0 only).
#define TBM  64
#define TBN  64
#define TBK  16
#define TBKP 20
template <int EPI, bool ATOMIC, bool TRANSA, bool TRANSC>
__global__ void __launch_bounds__(128)
mma_gemm_kernel(const float* __restrict__ A, const float* __restrict__ A2, int lda,
                const float* __restrict__ W, const float* __restrict__ Wb,
                float* __restrict__ C, int ldc,
                int M, int N, int K, int SK,
                const float* __restrict__ bias, const float* __restrict__ biasb,
                const float* __restrict__ pos, const float* __restrict__ temp,
                long strideA, long strideC) {
    __shared__ uint32_t As[2][TBM][TBKP];
    __shared__ uint32_t Bs[2][TBN][TBKP];

    int z = blockIdx.z;
    int dir = z / SK, ks = z - dir * SK;
    if (dir) { A += strideA; C += strideC; W = Wb; bias = biasb; if (A2) A2 += strideA; }
    int Kc = K / SK;
    int kbase = ks * Kc;
    int nk = Kc / TBK;

    int tid = threadIdx.x;
    int lane = tid & 31;
    int wid = tid >> 5;
    int wm = wid >> 1, wn = wid & 1;
    int qr = lane >> 2, qc = lane & 3;

    int rowBase = blockIdx.y * TBM;
    int colBase = blockIdx.x * TBN;

    auto load_tile = [&](int k0, int buf) {
        if (TRANSA) {
#pragma unroll
            for (int it = 0; it < 2; it++) {
                int item = it * 128 + tid;
                int kk = item >> 4;
                int r4 = (item & 15) * 4;
                float4 v = make_float4(0.f, 0.f, 0.f, 0.f);
                int row = rowBase + r4;
                if (row < M) {
                    v = *(const float4*)&A[(long)(k0 + kk) * lda + row];
                    if (A2) {
                        float4 w = *(const float4*)&A2[(long)(k0 + kk) * lda + row];
                        v.x += w.x; v.y += w.y; v.z += w.z; v.w += w.w;
                    }
                }
                As[buf][r4 + 0][kk] = f2tf32(v.x);
                As[buf][r4 + 1][kk] = f2tf32(v.y);
                As[buf][r4 + 2][kk] = f2tf32(v.z);
                As[buf][r4 + 3][kk] = f2tf32(v.w);
            }
        } else {
            int lr = tid >> 1;
            int lc = (tid & 1) * 8;
            int r = rowBase + lr;
            float4 a0 = make_float4(0.f, 0.f, 0.f, 0.f);
            float4 a1 = make_float4(0.f, 0.f, 0.f, 0.f);
            if (r < M) {
                a0 = *(const float4*)&A[(long)r * lda + k0 + lc];
                a1 = *(const float4*)&A[(long)r * lda + k0 + lc + 4];
                if (A2) {
                    float4 w0 = *(const float4*)&A2[(long)r * lda + k0 + lc];
                    float4 w1 = *(const float4*)&A2[(long)r * lda + k0 + lc + 4];
                    a0.x += w0.x; a0.y += w0.y; a0.z += w0.z; a0.w += w0.w;
                    a1.x += w1.x; a1.y += w1.y; a1.z += w1.z; a1.w += w1.w;
                }
            }
            As[buf][lr][lc + 0] = f2tf32(a0.x); As[buf][lr][lc + 1] = f2tf32(a0.y);
            As[buf][lr][lc + 2] = f2tf32(a0.z); As[buf][lr][lc + 3] = f2tf32(a0.w);
            As[buf][lr][lc + 4] = f2tf32(a1.x); As[buf][lr][lc + 5] = f2tf32(a1.y);
            As[buf][lr][lc + 6] = f2tf32(a1.z); As[buf][lr][lc + 7] = f2tf32(a1.w);
        }
        {
            int lr = tid >> 1;
            int lc = (tid & 1) * 8;
            int col = colBase + lr;
            float4 b0 = make_float4(0.f, 0.f, 0.f, 0.f);
            float4 b1 = make_float4(0.f, 0.f, 0.f, 0.f);
            if (col < N) {
                b0 = *(const float4*)&W[(long)col * K + k0 + lc];
                b1 = *(const float4*)&W[(long)col * K + k0 + lc + 4];
            }
            Bs[buf][lr][lc + 0] = f2tf32(b0.x); Bs[buf][lr][lc + 1] = f2tf32(b0.y);
            Bs[buf][lr][lc + 2] = f2tf32(b0.z); Bs[buf][lr][lc + 3] = f2tf32(b0.w);
            Bs[buf][lr][lc + 4] = f2tf32(b1.x); Bs[buf][lr][lc + 5] = f2tf32(b1.y);
            Bs[buf][lr][lc + 6] = f2tf32(b1.z); Bs[buf][lr][lc + 7] = f2tf32(b1.w);
        }
    };

    float acc[2][4][4];
#pragma unroll
    for (int mi = 0; mi < 2; mi++)
#pragma unroll
        for (int ni = 0; ni < 4; ni++)
#pragma unroll
            for (int u = 0; u < 4; u++) acc[mi][ni][u] = 0.f;

    load_tile(kbase, 0);
    __syncthreads();

    for (int c = 0; c < nk; c++) {
        int cur = c & 1, nxt = cur ^ 1;
        if (c + 1 < nk) load_tile(kbase + (c + 1) * TBK, nxt);
#pragma unroll
        for (int c2 = 0; c2 < 2; c2++) {
            uint32_t af[2][4], bf[4][2];
#pragma unroll
            for (int mi = 0; mi < 2; mi++) {
                int r = wm * 32 + mi * 16 + qr;
                af[mi][0] = As[cur][r][c2 * 8 + qc];
                af[mi][1] = As[cur][r + 8][c2 * 8 + qc];
                af[mi][2] = As[cur][r][c2 * 8 + 4 + qc];
                af[mi][3] = As[cur][r + 8][c2 * 8 + 4 + qc];
            }
#pragma unroll
            for (int ni = 0; ni < 4; ni++) {
                int n = wn * 32 + ni * 8 + qr;
                bf[ni][0] = Bs[cur][n][c2 * 8 + qc];
                bf[ni][1] = Bs[cur][n][c2 * 8 + 4 + qc];
            }
#pragma unroll
            for (int mi = 0; mi < 2; mi++)
#pragma unroll
                for (int ni = 0; ni < 4; ni++)
                    mma_tf32(acc[mi][ni], af[mi], bf[ni]);
        }
        __syncthreads();
    }

    if (TRANSC) {
        __shared__ float stage[TBN][68];
#pragma unroll
        for (int mi = 0; mi < 2; mi++) {
#pragma unroll
            for (int ni = 0; ni < 4; ni++) {
                int r0 = wm * 32 + mi * 16 + qr;
                int c0 = wn * 32 + ni * 8 + 2 * qc;
#pragma unroll
                for (int u = 0; u < 4; u++) {
                    int rl = r0 + (u >= 2 ? 8 : 0);
                    int cl = c0 + (u & 1);
                    float v = acc[mi][ni][u];
                    if (EPI == 1) v = softplusf(v + bias[colBase + cl]);
                    stage[cl][rl] = v;
                }
            }
        }
        __syncthreads();
#pragma unroll
        for (int it = 0; it < 8; it++) {
            int item = it * 128 + tid;
            int col = item >> 4;
            int r = (item & 15) * 4;
            int row = rowBase + r;
            if (row < M) {
                float4 v = *(const float4*)&stage[col][r];
                *(float4*)&C[(long)(colBase + col) * ldc + row] = v;
            }
        }
    } else {
#pragma unroll
        for (int mi = 0; mi < 2; mi++) {
#pragma unroll
            for (int ni = 0; ni < 4; ni++) {
                int r0 = rowBase + wm * 32 + mi * 16 + qr;
                int c0 = colBase + wn * 32 + ni * 8 + 2 * qc;
#pragma unroll
                for (int u = 0; u < 4; u++) {
                    int row = r0 + (u >= 2 ? 8 : 0);
                    int col = c0 + (u & 1);
                    if (row >= M || col >= N) continue;
                    float v = acc[mi][ni][u];
                    if (EPI == 1) {
                        v = softplusf(v + bias[col]);
                    } else if (EPI == 2) {
                        if (ks == 0) {
                            int tl = row % LSEQ;
                            int t = tl / NPATCH, p = tl % NPATCH;
                            v += bias[col] + pos[p * DM + col] + temp[t * DM + col];
                        }
                    }
                    if (ATOMIC) atomicAdd(&C[(long)row * ldc + col], v);
                    else        C[(long)row * ldc + col] = v;
                }
            }
        }
    }
}

// ---------------- residual add + rmsnorm (zeroes g_hidden and g_dbl) ----------
__global__ void __launch_bounds__(128)
addnorm_kernel(const float* __restrict__ w, int first) {
    int wid = threadIdx.x >> 5, lane = threadIdx.x & 31;
    int n = blockIdx.x * 4 + wid;
    int gt = blockIdx.x * 128 + threadIdx.x;
    if (gt < 2 * NT * 48 / 4) ((float4*)g_dbl)[gt] = make_float4(0.f, 0.f, 0.f, 0.f);

    float4* hp = (float4*)(g_hidden + (long)n * DM);
    float4* rp = (float4*)(g_resid + (long)n * DM);
    float4* op = (float4*)(g_hnorm + (long)n * DM);
    float4 h0 = hp[lane], h1 = hp[32 + lane];
    if (!first) {
        float4 r0 = rp[lane], r1 = rp[32 + lane];
        h0.x += r0.x; h0.y += r0.y; h0.z += r0.z; h0.w += r0.w;
        h1.x += r1.x; h1.y += r1.y; h1.z += r1.z; h1.w += r1.w;
    }
    rp[lane] = h0; rp[32 + lane] = h1;
    float4 zero = make_float4(0.f, 0.f, 0.f, 0.f);
    hp[lane] = zero; hp[32 + lane] = zero;
    float ss = h0.x*h0.x + h0.y*h0.y + h0.z*h0.z + h0.w*h0.w
             + h1.x*h1.x + h1.y*h1.y + h1.z*h1.z + h1.w*h1.w;
#pragma unroll
    for (int m = 16; m; m >>= 1) ss += __shfl_xor_sync(0xffffffffu, ss, m);
    float sc = rsqrtf(ss / (float)DM + 1e-5f);
    const float4* wp = (const float4*)w;
    float4 w0 = wp[lane], w1 = wp[32 + lane];
    op[lane]      = make_float4(h0.x*sc*w0.x, h0.y*sc*w0.y, h0.z*sc*w0.z, h0.w*sc*w0.w);
    op[32 + lane] = make_float4(h1.x*sc*w1.x, h1.y*sc*w1.y, h1.z*sc*w1.z, h1.w*sc*w1.w);
}

// ---------------- conv + silu + transpose  (and z-gate transpose) -------------
// Also resets the scan chain tickets/counters for this layer (block (0,0,0)).
#define CT 64
#define CD 32
__global__ void __launch_bounds__(256)
conv_kernel(const float* __restrict__ cwf, const float* __restrict__ cbf,
            const float* __restrict__ cwb, const float* __restrict__ cbb) {
    if (blockIdx.x == 0 && blockIdx.y == 0 && blockIdx.z == 0 && threadIdx.x < NCHAIN) {
        g_ticket[threadIdx.x] = 0;
        g_done[threadIdx.x] = 0;
    }
    __shared__ float tile[CT + 3][CD + 1];
    int mode = blockIdx.z / BB;
    int b = blockIdx.z % BB;
    int t0 = blockIdx.x * CT;
    int d0 = blockIdx.y * CD;
    int tid = threadIdx.x;
    int colbase = (mode == 2 ? DI : 0) + d0;

    int rr = tid >> 3, cc = (tid & 7) * 4;
#pragma unroll
    for (int it = 0; it < 3; it++) {
        int r = it * 32 + rr;
        if (r < CT + 3) {
            int ss = t0 - 3 + r;
            float4 v = make_float4(0.f, 0.f, 0.f, 0.f);
            if (ss >= 0 && ss < LSEQ) {
                int src = (mode == 1) ? (LSEQ - 1 - ss) : ss;
                v = *(const float4*)&g_xz[(long)(b * LSEQ + src) * (2 * DI) + colbase + cc];
            }
            tile[r][cc + 0] = v.x; tile[r][cc + 1] = v.y;
            tile[r][cc + 2] = v.z; tile[r][cc + 3] = v.w;
        }
    }
    __syncthreads();

    int tl = tid & 63, dg = tid >> 6;
    int tt = t0 + tl;
    if (tt >= LSEQ) return;
    if (mode == 2) {
#pragma unroll
        for (int i = 0; i < 8; i++) {
            int dl = dg * 8 + i;
            float v = siluf(tile[tl + 3][dl]);
            g_gz[(long)(d0 + dl) * NT + b * LSEQ + tt] = v;
        }
    } else {
        const float* cw = mode ? cwb : cwf;
        const float* cb = mode ? cbb : cbf;
#pragma unroll
        for (int i = 0; i < 8; i++) {
            int dl = dg * 8 + i;
            int d = d0 + dl;
            float acc = cb[d];
#pragma unroll
            for (int k = 0; k < 4; k++)
                acc = fmaf(tile[tl + k][dl], cw[d * 4 + k], acc);
            g_xs[((long)mode * DI + d) * NT + b * LSEQ + tt] = siluf(acc);
        }
    }
}

// ---------------- single-kernel chained SSM scan ------------------------------
// Tickets assign chunks in block-arrival order (deadlock-free: the block that
// owns chunk c-1 started no later than the one that owns chunk c, so every
// waiter waits on an already-running block). Release/acquire via threadfence.
__global__ void __launch_bounds__(256)
scan_kernel(int layer, const float* __restrict__ Dsf, const float* __restrict__ Dsb) {
    int dir = blockIdx.z;
    int bx = blockIdx.x;
    int tid = threadIdx.x;
    int grp = tid >> 4, s = tid & 15;
    int chain = dir * 64 + bx;

    __shared__ int s_c;
    if (tid == 0) s_c = atomicAdd(&g_ticket[chain], 1);
    __syncthreads();
    int c = s_c;

    int ch = bx * 16 + grp;
    int b = ch >> 9, d = ch & (DI - 1);
    int e = ((dir * BB + b) * DI + d) * DSTATE + s;

    const float A_ds = g_A[(dir * NDEPTH + layer) * DI * DSTATE + d * DSTATE + s];
    const float Dd = (dir ? Dsb : Dsf)[d];
    long base = ((long)dir * DI + d) * NT + b * LSEQ;
    const float* dtp = g_dt + base;
    const float* xsp = g_xs + base;
    const float* dblp = g_dbl + ((long)dir * NT + b * LSEQ) * 48;
    const float* gzp = g_gz + (long)d * NT + b * LSEQ;
    float* yp = g_y + base;

    float h = 0.f;
    if (c > 0) {
        if (tid == 0) {
            while (atomicAdd(&g_done[chain], 0) < c) __nanosleep(60);
        }
        __syncthreads();
        __threadfence();          // acquire: order hbuf read after flag observation
        h = g_hbuf[e];
    }

    int t0 = c * CLEN;
    float yb0 = 0.f, yb1 = 0.f, yb2 = 0.f;
    for (int tb = 0; tb < CLEN; tb += 16) {
        int tt = t0 + tb;
        float dtv = dtp[tt + s];
        float uv  = xsp[tt + s];
#pragma unroll
        for (int j = 0; j < 16; j++) {
            int ss = tt + j;
            float dt = __shfl_sync(0xffffffffu, dtv, j, 16);
            float u  = __shfl_sync(0xffffffffu, uv,  j, 16);
            float Bv = dblp[ss * 48 + 16 + s];
            float Cv = dblp[ss * 48 + 32 + s];
            float a = __expf(dt * A_ds);
            h = fmaf(a, h, (dt * u) * Bv);
            float p = h * Cv;
            p += __shfl_xor_sync(0xffffffffu, p, 8);
            p += __shfl_xor_sync(0xffffffffu, p, 4);
            p += __shfl_xor_sync(0xffffffffu, p, 2);
            p += __shfl_xor_sync(0xffffffffu, p, 1);
            if (s == 0) {
                int orig = dir ? (LSEQ - 1 - ss) : ss;
                float val = (p + Dd * u) * gzp[orig];
                if ((j & 3) == 0) yb0 = val;
                else if ((j & 3) == 1) yb1 = val;
                else if ((j & 3) == 2) yb2 = val;
                else {
                    float4 o = dir ? make_float4(val, yb2, yb1, yb0)
                                   : make_float4(yb0, yb1, yb2, val);
                    int addr = dir ? (LSEQ - 1 - ss) : (ss - 3);
                    *(float4*)&yp[addr] = o;
                }
            }
        }
    }

    // publish exit state for next chunk (release ordering)
    if (c < NCHUNK - 1) {
        g_hbuf[e] = h;
        __threadfence();
        __syncthreads();
        if (tid == 0) atomicExch(&g_done[chain], c + 1);
    }
}

// ---------------- final norm + heads ------------------------------------------
__global__ void finalnorm_kernel(const float* __restrict__ w) {
    int bi = blockIdx.x;
    int c = threadIdx.x;
    int b = bi / 5, tok = bi % 5;
    int n = b * LSEQ + tok;
    float r = g_resid[n * DM + c] + g_hidden[n * DM + c];
    float ss = r * r;
#pragma unroll
    for (int m = 16; m; m >>= 1) ss += __shfl_xor_sync(0xffffffffu, ss, m);
    __shared__ float sw[8];
    if ((c & 31) == 0) sw[c >> 5] = ss;
    __syncthreads();
    float tot = 0.f;
#pragma unroll
    for (int i = 0; i < 8; i++) tot += sw[i];
    float sc = rsqrtf(tot / (float)DM + 1e-5f);
    g_fus[bi * DM + c] = r * sc * w[c];
}

__global__ void heads_kernel(const float* __restrict__ bw1, const float* __restrict__ bb1,
                             const float* __restrict__ bw2, const float* __restrict__ bb2,
                             const float* __restrict__ pw1, const float* __restrict__ pb1,
                             const float* __restrict__ pw2, const float* __restrict__ pb2,
                             float* __restrict__ out) {
    int h = blockIdx.x;
    int b = blockIdx.y;
    int tid = threadIdx.x;
    __shared__ float sin_[DM];
    __shared__ float hidv[DM];
    sin_[tid] = g_fus[(b * 5 + h) * DM + tid];
    __syncthreads();

    const float *w1, *b1, *w2, *b2;
    int nout; bool sig;
    if (h == 0) { w1 = bw1; b1 = bb1; w2 = bw2; b2 = bb2; nout = 3; sig = false; }
    else {
        int i = h - 1;
        w1 = pw1 + (long)i * DM * DM; b1 = pb1 + i * DM;
        w2 = pw2 + i * 2 * DM;        b2 = pb2 + i * 2;
        nout = 2; sig = true;
    }
    float acc = b1[tid];
    for (int k = 0; k < DM; k++) acc = fmaf(sin_[k], w1[(long)tid * DM + k], acc);
    hidv[tid] = fmaxf(acc, 0.f);
    __syncthreads();

    int w = tid >> 5, lane = tid & 31;
    if (w < nout) {
        float a = 0.f;
        for (int k = lane; k < DM; k += 32) a += hidv[k] * w2[w * DM + k];
#pragma unroll
        for (int m = 16; m; m >>= 1) a += __shfl_xor_sync(0xffffffffu, a, m);
        if (lane == 0) {
            float v = a + b2[w];
            if (sig) v = 1.f / (1.f + __expf(-v));
            int o = (h == 0) ? (b * 11 + w) : (b * 11 + 3 + (h - 1) * 2 + w);
            out[o] = v;
        }
    }
}

// ---------------- host side ----------------
extern "C" void kernel_launch(void* const* d_in, const int* in_sizes, int n_in,
                              void* d_out, int out_size) {
    (void)in_sizes; (void)n_in; (void)out_size;
    const float* x        = (const float*)d_in[0];
    const float* patch_w  = (const float*)d_in[1];
    const float* patch_b  = (const float*)d_in[2];
    const float* pos      = (const float*)d_in[3];
    const float* temp     = (const float*)d_in[4];
    const float* in_proj  = (const float*)d_in[5];
    const float* convf_w  = (const float*)d_in[6];
    const float* convf_b  = (const float*)d_in[7];
    const float* xprojf   = (const float*)d_in[8];
    const float* dtf_w    = (const float*)d_in[9];
    const float* dtf_b    = (const float*)d_in[10];
    const float* A_logf   = (const float*)d_in[11];
    const float* Dsf      = (const float*)d_in[12];
    const float* convb_w  = (const float*)d_in[13];
    const float* convb_b  = (const float*)d_in[14];
    const float* xprojb   = (const float*)d_in[15];
    const float* dtb_w    = (const float*)d_in[16];
    const float* dtb_b    = (const float*)d_in[17];
    const float* A_logb   = (const float*)d_in[18];
    const float* Dsb      = (const float*)d_in[19];
    const float* out_proj = (const float*)d_in[20];
    const float* norm_w   = (const float*)d_in[21];
    const float* normf_w  = (const float*)d_in[22];
    const float* bbox_w1  = (const float*)d_in[23];
    const float* bbox_b1  = (const float*)d_in[24];
    const float* bbox_w2  = (const float*)d_in[25];
    const float* bbox_b2  = (const float*)d_in[26];
    const float* pix_w1   = (const float*)d_in[27];
    const float* pix_b1   = (const float*)d_in[28];
    const float* pix_w2   = (const float*)d_in[29];
    const float* pix_b2   = (const float*)d_in[30];
    float* out = (float*)d_out;

    float *p_im2col, *p_hidden, *p_hnorm, *p_xz, *p_xs, *p_dbl, *p_dt, *p_y;
    cudaGetSymbolAddress((void**)&p_im2col, g_im2col);
    cudaGetSymbolAddress((void**)&p_hidden, g_hidden);
    cudaGetSymbolAddress((void**)&p_hnorm,  g_hnorm);
    cudaGetSymbolAddress((void**)&p_xz,     g_xz);
    cudaGetSymbolAddress((void**)&p_xs,     g_xs);
    cudaGetSymbolAddress((void**)&p_dbl,    g_dbl);
    cudaGetSymbolAddress((void**)&p_dt,     g_dt);
    cudaGetSymbolAddress((void**)&p_y,      g_y);

    const int GY = (NT + TBM - 1) / TBM;   // 25

    prep_A_kernel<<<(NDEPTH * DI * DSTATE + 255) / 256, 256>>>(A_logf, A_logb);
    im2col_kernel<<<(NT * KPATCH + 255) / 256, 256>>>(x);

    // patch embed: N=256, K=768, split-K 2, atomic, EPI=2
    mma_gemm_kernel<2, true, false, false><<<dim3(4, GY, 2), 128>>>(
        p_im2col, nullptr, KPATCH, patch_w, nullptr, p_hidden, DM,
        NT, DM, KPATCH, 2, patch_b, nullptr, pos, temp, 0, 0);

    for (int i = 0; i < NDEPTH; i++) {
        addnorm_kernel<<<NT / 4, 128>>>(norm_w + i * DM, i == 0);
        // in_proj: N=1024, K=256
        mma_gemm_kernel<0, false, false, false><<<dim3(16, GY, 1), 128>>>(
            p_hnorm, nullptr, DM, in_proj + (long)i * 2 * DI * DM, nullptr,
            p_xz, 2 * DI, NT, 2 * DI, DM, 1, nullptr, nullptr, nullptr, nullptr, 0, 0);
        // conv + silu + transpose (fwd, bwd, z-gate); also resets scan chains
        conv_kernel<<<dim3((LSEQ + CT - 1) / CT, DI / CD, 3 * BB), 256>>>(
            convf_w + (long)i * DI * 4, convf_b + i * DI,
            convb_w + (long)i * DI * 4, convb_b + i * DI);
        // xproj: A = xs_T (TRANSA), N=48, K=512, dirs 2, split-K 2, atomic
        mma_gemm_kernel<0, true, true, false><<<dim3(1, GY, 4), 128>>>(
            p_xs, nullptr, NT, xprojf + (long)i * 48 * DI, xprojb + (long)i * 48 * DI,
            p_dbl, 48, NT, 48, DI, 2, nullptr, nullptr, nullptr, nullptr,
            (long)DI * NT, (long)NT * 48);
        // dt: N=512, K=16, dirs 2, softplus, TRANSC -> dt_T
        mma_gemm_kernel<1, false, false, true><<<dim3(8, GY, 2), 128>>>(
            p_dbl, nullptr, 48, dtf_w + (long)i * DI * DTR, dtb_w + (long)i * DI * DTR,
            p_dt, NT, NT, DI, DTR, 1, dtf_b + i * DI, dtb_b + i * DI, nullptr, nullptr,
            (long)NT * 48, (long)DI * NT);
        // single-kernel chained scan
        scan_kernel<<<dim3(64, NCHUNK, 2), 256>>>(i, Dsf + i * DI, Dsb + i * DI);
        // out_proj: A = y_T fwd + bwd (TRANSA), N=256, K=512, split-K 2, atomic
        mma_gemm_kernel<0, true, true, false><<<dim3(4, GY, 2), 128>>>(
            p_y, p_y + (long)DI * NT, NT, out_proj + (long)i * DM * DI, nullptr,
            p_hidden, DM, NT, DM, DI, 2, nullptr, nullptr, nullptr, nullptr, 0, 0);
    }

    finalnorm_kernel<<<BB * 5, 256>>>(normf_w);
    heads_kernel<<<dim3(5, BB), 256>>>(bbox_w1, bbox_b1, bbox_w2, bbox_b2,
                                       pix_w1, pix_b1, pix_w2, pix_b2, out);
}

// round 11
// speedup vs baseline: 1.9040x; 1.9040x over previous
#include <cuda_runtime.h>
#include <math.h>
#include <stdint.h>

#define BB      2
#define FRAMES  4
#define LSEQ    784
#define NT      1568
#define DM      256
#define DI      512
#define DSTATE  16
#define DTR     16
#define NDEPTH  12
#define NPATCH  196
#define KPATCH  768
#define NCHUNK  7
#define CLEN    112
#define NGRP    (2 * BB * DI * DSTATE)

// ---------------- scratch ----------------
__device__ float g_im2col[NT * KPATCH];
__device__ float g_hidden[NT * DM];
__device__ float g_resid [NT * DM];
__device__ float g_hnorm [NT * DM];
__device__ float g_xz    [NT * 2 * DI];
__device__ float g_xs    [2 * DI * NT];   // TRANSPOSED: [dir][d][b*784+t]
__device__ float g_gz    [DI * NT];       // TRANSPOSED silu(z)
__device__ float g_dbl   [2 * NT * 48];
__device__ float g_dt    [2 * DI * NT];   // TRANSPOSED
__device__ float g_y     [2 * DI * NT];   // TRANSPOSED
__device__ float g_A     [2 * NDEPTH * DI * DSTATE];
__device__ float g_fus   [BB * 5 * DM];
__device__ float g_P     [NCHUNK][NGRP];
__device__ float g_q     [NCHUNK][NGRP];

static __device__ __forceinline__ float siluf(float x) {
    return x / (1.f + __expf(-x));
}
static __device__ __forceinline__ float softplusf(float x) {
    return (x > 20.f) ? x : log1pf(__expf(x));
}
static __device__ __forceinline__ uint32_t f2tf32(float x) {
    uint32_t r;
    asm("cvt.rna.tf32.f32 %0, %1;" : "=r"(r) : "f"(x));
    return r;
}
static __device__ __forceinline__ void mma_tf32(float* d, const uint32_t* a, const uint32_t* b) {
    asm volatile(
        "mma.sync.aligned.m16n8k8.row.col.f32.tf32.tf32.f32 "
        "{%0,%1,%2,%3}, {%4,%5,%6,%7}, {%8,%9}, {%0,%1,%2,%3};"
        : "+f"(d[0]), "+f"(d[1]), "+f"(d[2]), "+f"(d[3])
        : "r"(a[0]), "r"(a[1]), "r"(a[2]), "r"(a[3]), "r"(b[0]), "r"(b[1]));
}

__global__ void prep_A_kernel(const float* __restrict__ Af, const float* __restrict__ Ab) {
    int e = blockIdx.x * blockDim.x + threadIdx.x;
    const int N = NDEPTH * DI * DSTATE;
    if (e < N) {
        g_A[e]     = -expf(Af[e]);
        g_A[N + e] = -expf(Ab[e]);
    }
}

__global__ void im2col_kernel(const float* __restrict__ x) {
    int e = blockIdx.x * blockDim.x + threadIdx.x;
    if (e >= NT * KPATCH) return;
    if (e < NT * DM) g_hidden[e] = 0.f;
    int n = e / KPATCH, k = e % KPATCH;
    int b = n / LSEQ, tl = n % LSEQ;
    int t = tl / NPATCH, p = tl % NPATCH;
    int ph = p / 14, pw = p % 14;
    int ci = k / 256, rem = k % 256;
    int ii = rem / 16, jj = rem % 16;
    long off = (((long)(b * 3 + ci) * FRAMES + t) * 224 + (ph * 16 + ii)) * 224 + (pw * 16 + jj);
    g_im2col[e] = x[off];
}

// ---------------- TF32 tensor-core GEMM, 64x64 tile, 4 warps ------------------
// C[M,N] = (A [+A2]) @ W^T ; W is N x K row-major. z = dir*SK + ks.
// TRANSA: A col-major A[k*lda + row]. TRANSC: C written transposed, smem-staged.
// EPI: 0 none, 1 softplus(+bias), 2 patch epilogue (ks==0 only).
// Smem k-layout is PERMUTED within each 8-wide k-group: col k stored at
// (k&3)*2 + (k>>2), so a thread's fragment pair (k=qc, k=qc+4) is adjacent
// and loads as one 64-bit LDS.
#define TBM  64
#define TBN  64
#define TBK  16
#define TBKP 20
template <int EPI, bool ATOMIC, bool TRANSA, bool TRANSC>
__global__ void __launch_bounds__(128)
mma_gemm_kernel(const float* __restrict__ A, const float* __restrict__ A2, int lda,
                const float* __restrict__ W, const float* __restrict__ Wb,
                float* __restrict__ C, int ldc,
                int M, int N, int K, int SK,
                const float* __restrict__ bias, const float* __restrict__ biasb,
                const float* __restrict__ pos, const float* __restrict__ temp,
                long strideA, long strideC) {
    __shared__ uint32_t As[2][TBM][TBKP];
    __shared__ uint32_t Bs[2][TBN][TBKP];

    int z = blockIdx.z;
    int dir = z / SK, ks = z - dir * SK;
    if (dir) { A += strideA; C += strideC; W = Wb; bias = biasb; if (A2) A2 += strideA; }
    int Kc = K / SK;
    int kbase = ks * Kc;
    int nk = Kc / TBK;

    int tid = threadIdx.x;
    int lane = tid & 31;
    int wid = tid >> 5;
    int wm = wid >> 1, wn = wid & 1;
    int qr = lane >> 2, qc = lane & 3;

    int rowBase = blockIdx.y * TBM;
    int colBase = blockIdx.x * TBN;

    auto load_tile = [&](int k0, int buf) {
        if (TRANSA) {
#pragma unroll
            for (int it = 0; it < 2; it++) {
                int item = it * 128 + tid;
                int kk = item >> 4;                         // 0..15
                int pcol = (kk & 8) + ((kk & 3) * 2) + ((kk >> 2) & 1);
                int r4 = (item & 15) * 4;
                float4 v = make_float4(0.f, 0.f, 0.f, 0.f);
                int row = rowBase + r4;
                if (row < M) {
                    v = *(const float4*)&A[(long)(k0 + kk) * lda + row];
                    if (A2) {
                        float4 w = *(const float4*)&A2[(long)(k0 + kk) * lda + row];
                        v.x += w.x; v.y += w.y; v.z += w.z; v.w += w.w;
                    }
                }
                As[buf][r4 + 0][pcol] = f2tf32(v.x);
                As[buf][r4 + 1][pcol] = f2tf32(v.y);
                As[buf][r4 + 2][pcol] = f2tf32(v.z);
                As[buf][r4 + 3][pcol] = f2tf32(v.w);
            }
        } else {
            int lr = tid >> 1;
            int lc = (tid & 1) * 8;
            int r = rowBase + lr;
            float4 a0 = make_float4(0.f, 0.f, 0.f, 0.f);
            float4 a1 = make_float4(0.f, 0.f, 0.f, 0.f);
            if (r < M) {
                a0 = *(const float4*)&A[(long)r * lda + k0 + lc];
                a1 = *(const float4*)&A[(long)r * lda + k0 + lc + 4];
                if (A2) {
                    float4 w0 = *(const float4*)&A2[(long)r * lda + k0 + lc];
                    float4 w1 = *(const float4*)&A2[(long)r * lda + k0 + lc + 4];
                    a0.x += w0.x; a0.y += w0.y; a0.z += w0.z; a0.w += w0.w;
                    a1.x += w1.x; a1.y += w1.y; a1.z += w1.z; a1.w += w1.w;
                }
            }
            // permuted within-group: k=0..3 -> 0,2,4,6 ; k=4..7 -> 1,3,5,7
            As[buf][lr][lc + 0] = f2tf32(a0.x); As[buf][lr][lc + 2] = f2tf32(a0.y);
            As[buf][lr][lc + 4] = f2tf32(a0.z); As[buf][lr][lc + 6] = f2tf32(a0.w);
            As[buf][lr][lc + 1] = f2tf32(a1.x); As[buf][lr][lc + 3] = f2tf32(a1.y);
            As[buf][lr][lc + 5] = f2tf32(a1.z); As[buf][lr][lc + 7] = f2tf32(a1.w);
        }
        {
            int lr = tid >> 1;
            int lc = (tid & 1) * 8;
            int col = colBase + lr;
            float4 b0 = make_float4(0.f, 0.f, 0.f, 0.f);
            float4 b1 = make_float4(0.f, 0.f, 0.f, 0.f);
            if (col < N) {
                b0 = *(const float4*)&W[(long)col * K + k0 + lc];
                b1 = *(const float4*)&W[(long)col * K + k0 + lc + 4];
            }
            Bs[buf][lr][lc + 0] = f2tf32(b0.x); Bs[buf][lr][lc + 2] = f2tf32(b0.y);
            Bs[buf][lr][lc + 4] = f2tf32(b0.z); Bs[buf][lr][lc + 6] = f2tf32(b0.w);
            Bs[buf][lr][lc + 1] = f2tf32(b1.x); Bs[buf][lr][lc + 3] = f2tf32(b1.y);
            Bs[buf][lr][lc + 5] = f2tf32(b1.z); Bs[buf][lr][lc + 7] = f2tf32(b1.w);
        }
    };

    float acc[2][4][4];
#pragma unroll
    for (int mi = 0; mi < 2; mi++)
#pragma unroll
        for (int ni = 0; ni < 4; ni++)
#pragma unroll
            for (int u = 0; u < 4; u++) acc[mi][ni][u] = 0.f;

    load_tile(kbase, 0);
    __syncthreads();

    for (int c = 0; c < nk; c++) {
        int cur = c & 1, nxt = cur ^ 1;
        if (c + 1 < nk) load_tile(kbase + (c + 1) * TBK, nxt);
#pragma unroll
        for (int c2 = 0; c2 < 2; c2++) {
            int co = c2 * 8 + 2 * qc;       // permuted: {k=qc, k=qc+4} adjacent
            uint32_t af[2][4], bf[4][2];
#pragma unroll
            for (int mi = 0; mi < 2; mi++) {
                int r = wm * 32 + mi * 16 + qr;
                uint2 v0 = *(const uint2*)&As[cur][r][co];
                uint2 v1 = *(const uint2*)&As[cur][r + 8][co];
                af[mi][0] = v0.x; af[mi][1] = v1.x;
                af[mi][2] = v0.y; af[mi][3] = v1.y;
            }
#pragma unroll
            for (int ni = 0; ni < 4; ni++) {
                int n = wn * 32 + ni * 8 + qr;
                uint2 w = *(const uint2*)&Bs[cur][n][co];
                bf[ni][0] = w.x; bf[ni][1] = w.y;
            }
#pragma unroll
            for (int mi = 0; mi < 2; mi++)
#pragma unroll
                for (int ni = 0; ni < 4; ni++)
                    mma_tf32(acc[mi][ni], af[mi], bf[ni]);
        }
        __syncthreads();
    }

    if (TRANSC) {
        __shared__ float stage[TBN][68];
#pragma unroll
        for (int mi = 0; mi < 2; mi++) {
#pragma unroll
            for (int ni = 0; ni < 4; ni++) {
                int r0 = wm * 32 + mi * 16 + qr;
                int c0 = wn * 32 + ni * 8 + 2 * qc;
#pragma unroll
                for (int u = 0; u < 4; u++) {
                    int rl = r0 + (u >= 2 ? 8 : 0);
                    int cl = c0 + (u & 1);
                    float v = acc[mi][ni][u];
                    if (EPI == 1) v = softplusf(v + bias[colBase + cl]);
                    stage[cl][rl] = v;
                }
            }
        }
        __syncthreads();
#pragma unroll
        for (int it = 0; it < 8; it++) {
            int item = it * 128 + tid;
            int col = item >> 4;
            int r = (item & 15) * 4;
            int row = rowBase + r;
            if (row < M) {
                float4 v = *(const float4*)&stage[col][r];
                *(float4*)&C[(long)(colBase + col) * ldc + row] = v;
            }
        }
    } else {
#pragma unroll
        for (int mi = 0; mi < 2; mi++) {
#pragma unroll
            for (int ni = 0; ni < 4; ni++) {
                int r0 = rowBase + wm * 32 + mi * 16 + qr;
                int c0 = colBase + wn * 32 + ni * 8 + 2 * qc;
#pragma unroll
                for (int u = 0; u < 4; u++) {
                    int row = r0 + (u >= 2 ? 8 : 0);
                    int col = c0 + (u & 1);
                    if (row >= M || col >= N) continue;
                    float v = acc[mi][ni][u];
                    if (EPI == 1) {
                        v = softplusf(v + bias[col]);
                    } else if (EPI == 2) {
                        if (ks == 0) {
                            int tl = row % LSEQ;
                            int t = tl / NPATCH, p = tl % NPATCH;
                            v += bias[col] + pos[p * DM + col] + temp[t * DM + col];
                        }
                    }
                    if (ATOMIC) atomicAdd(&C[(long)row * ldc + col], v);
                    else        C[(long)row * ldc + col] = v;
                }
            }
        }
    }
}

// ---------------- residual add + rmsnorm (zeroes g_hidden and g_dbl) ----------
__global__ void __launch_bounds__(128)
addnorm_kernel(const float* __restrict__ w, int first) {
    int wid = threadIdx.x >> 5, lane = threadIdx.x & 31;
    int n = blockIdx.x * 4 + wid;
    int gt = blockIdx.x * 128 + threadIdx.x;
    if (gt < 2 * NT * 48 / 4) ((float4*)g_dbl)[gt] = make_float4(0.f, 0.f, 0.f, 0.f);

    float4* hp = (float4*)(g_hidden + (long)n * DM);
    float4* rp = (float4*)(g_resid + (long)n * DM);
    float4* op = (float4*)(g_hnorm + (long)n * DM);
    float4 h0 = hp[lane], h1 = hp[32 + lane];
    if (!first) {
        float4 r0 = rp[lane], r1 = rp[32 + lane];
        h0.x += r0.x; h0.y += r0.y; h0.z += r0.z; h0.w += r0.w;
        h1.x += r1.x; h1.y += r1.y; h1.z += r1.z; h1.w += r1.w;
    }
    rp[lane] = h0; rp[32 + lane] = h1;
    float4 zero = make_float4(0.f, 0.f, 0.f, 0.f);
    hp[lane] = zero; hp[32 + lane] = zero;
    float ss = h0.x*h0.x + h0.y*h0.y + h0.z*h0.z + h0.w*h0.w
             + h1.x*h1.x + h1.y*h1.y + h1.z*h1.z + h1.w*h1.w;
#pragma unroll
    for (int m = 16; m; m >>= 1) ss += __shfl_xor_sync(0xffffffffu, ss, m);
    float sc = rsqrtf(ss / (float)DM + 1e-5f);
    const float4* wp = (const float4*)w;
    float4 w0 = wp[lane], w1 = wp[32 + lane];
    op[lane]      = make_float4(h0.x*sc*w0.x, h0.y*sc*w0.y, h0.z*sc*w0.z, h0.w*sc*w0.w);
    op[32 + lane] = make_float4(h1.x*sc*w1.x, h1.y*sc*w1.y, h1.z*sc*w1.z, h1.w*sc*w1.w);
}

// ---------------- conv + silu + transpose  (and z-gate transpose) -------------
#define CT 64
#define CD 32
__global__ void __launch_bounds__(256)
conv_kernel(const float* __restrict__ cwf, const float* __restrict__ cbf,
            const float* __restrict__ cwb, const float* __restrict__ cbb) {
    __shared__ float tile[CT + 3][CD + 1];
    int mode = blockIdx.z / BB;
    int b = blockIdx.z % BB;
    int t0 = blockIdx.x * CT;
    int d0 = blockIdx.y * CD;
    int tid = threadIdx.x;
    int colbase = (mode == 2 ? DI : 0) + d0;

    int rr = tid >> 3, cc = (tid & 7) * 4;
#pragma unroll
    for (int it = 0; it < 3; it++) {
        int r = it * 32 + rr;
        if (r < CT + 3) {
            int ss = t0 - 3 + r;
            float4 v = make_float4(0.f, 0.f, 0.f, 0.f);
            if (ss >= 0 && ss < LSEQ) {
                int src = (mode == 1) ? (LSEQ - 1 - ss) : ss;
                v = *(const float4*)&g_xz[(long)(b * LSEQ + src) * (2 * DI) + colbase + cc];
            }
            tile[r][cc + 0] = v.x; tile[r][cc + 1] = v.y;
            tile[r][cc + 2] = v.z; tile[r][cc + 3] = v.w;
        }
    }
    __syncthreads();

    int tl = tid & 63, dg = tid >> 6;
    int tt = t0 + tl;
    if (tt >= LSEQ) return;
    if (mode == 2) {
#pragma unroll
        for (int i = 0; i < 8; i++) {
            int dl = dg * 8 + i;
            float v = siluf(tile[tl + 3][dl]);
            g_gz[(long)(d0 + dl) * NT + b * LSEQ + tt] = v;
        }
    } else {
        const float* cw = mode ? cwb : cwf;
        const float* cb = mode ? cbb : cbf;
#pragma unroll
        for (int i = 0; i < 8; i++) {
            int dl = dg * 8 + i;
            int d = d0 + dl;
            float acc = cb[d];
#pragma unroll
            for (int k = 0; k < 4; k++)
                acc = fmaf(tile[tl + k][dl], cw[d * 4 + k], acc);
            g_xs[((long)mode * DI + d) * NT + b * LSEQ + tt] = siluf(acc);
        }
    }
}

// ---------------- chunked SSM scan (two-pass, transposed inputs) --------------
__global__ void scan_pass1_kernel(int layer) {
    int dir = blockIdx.z;
    int c = blockIdx.y;
    int tid = threadIdx.x;
    int grp = tid >> 4, s = tid & 15;
    int ch = blockIdx.x * 16 + grp;
    int b = ch >> 9, d = ch & (DI - 1);
    int e = ((dir * BB + b) * DI + d) * DSTATE + s;

    const float A_ds = g_A[(dir * NDEPTH + layer) * DI * DSTATE + d * DSTATE + s];
    long base = ((long)dir * DI + d) * NT + b * LSEQ;
    const float* dtp = g_dt + base;
    const float* xsp = g_xs + base;
    const float* dblp = g_dbl + ((long)dir * NT + b * LSEQ) * 48;

    float P = 1.f, q = 0.f;
    int t0 = c * CLEN;
    for (int tb = 0; tb < CLEN; tb += 16) {
        int tt = t0 + tb;
        float dtv = dtp[tt + s];
        float uv  = xsp[tt + s];
#pragma unroll
        for (int j = 0; j < 16; j++) {
            float dt = __shfl_sync(0xffffffffu, dtv, j, 16);
            float u  = __shfl_sync(0xffffffffu, uv,  j, 16);
            float Bv = dblp[(tt + j) * 48 + 16 + s];
            float a = __expf(dt * A_ds);
            P *= a;
            q = fmaf(a, q, (dt * u) * Bv);
        }
    }
    g_P[c][e] = P;
    g_q[c][e] = q;
}

__global__ void scan_pass2_kernel(int layer, const float* __restrict__ Dsf,
                                  const float* __restrict__ Dsb) {
    int dir = blockIdx.z;
    int c = blockIdx.y;
    int tid = threadIdx.x;
    int grp = tid >> 4, s = tid & 15;
    int ch = blockIdx.x * 16 + grp;
    int b = ch >> 9, d = ch & (DI - 1);
    int e = ((dir * BB + b) * DI + d) * DSTATE + s;

    const float A_ds = g_A[(dir * NDEPTH + layer) * DI * DSTATE + d * DSTATE + s];
    const float Dd = (dir ? Dsb : Dsf)[d];
    long base = ((long)dir * DI + d) * NT + b * LSEQ;
    const float* dtp = g_dt + base;
    const float* xsp = g_xs + base;
    const float* dblp = g_dbl + ((long)dir * NT + b * LSEQ) * 48;
    const float* gzp = g_gz + (long)d * NT + b * LSEQ;
    float* yp = g_y + base;

    float h = 0.f;
    for (int cc = 0; cc < c; cc++) h = fmaf(g_P[cc][e], h, g_q[cc][e]);

    int t0 = c * CLEN;
    float yb0 = 0.f, yb1 = 0.f, yb2 = 0.f;
    for (int tb = 0; tb < CLEN; tb += 16) {
        int tt = t0 + tb;
        float dtv = dtp[tt + s];
        float uv  = xsp[tt + s];
#pragma unroll
        for (int j = 0; j < 16; j++) {
            int ss = tt + j;
            float dt = __shfl_sync(0xffffffffu, dtv, j, 16);
            float u  = __shfl_sync(0xffffffffu, uv,  j, 16);
            float Bv = dblp[ss * 48 + 16 + s];
            float Cv = dblp[ss * 48 + 32 + s];
            float a = __expf(dt * A_ds);
            h = fmaf(a, h, (dt * u) * Bv);
            float p = h * Cv;
            p += __shfl_xor_sync(0xffffffffu, p, 8);
            p += __shfl_xor_sync(0xffffffffu, p, 4);
            p += __shfl_xor_sync(0xffffffffu, p, 2);
            p += __shfl_xor_sync(0xffffffffu, p, 1);
            if (s == 0) {
                int orig = dir ? (LSEQ - 1 - ss) : ss;
                float val = (p + Dd * u) * gzp[orig];
                if ((j & 3) == 0) yb0 = val;
                else if ((j & 3) == 1) yb1 = val;
                else if ((j & 3) == 2) yb2 = val;
                else {
                    float4 o = dir ? make_float4(val, yb2, yb1, yb0)
                                   : make_float4(yb0, yb1, yb2, val);
                    int addr = dir ? (LSEQ - 1 - ss) : (ss - 3);
                    *(float4*)&yp[addr] = o;
                }
            }
        }
    }
}

// ---------------- final norm + heads ------------------------------------------
__global__ void finalnorm_kernel(const float* __restrict__ w) {
    int bi = blockIdx.x;
    int c = threadIdx.x;
    int b = bi / 5, tok = bi % 5;
    int n = b * LSEQ + tok;
    float r = g_resid[n * DM + c] + g_hidden[n * DM + c];
    float ss = r * r;
#pragma unroll
    for (int m = 16; m; m >>= 1) ss += __shfl_xor_sync(0xffffffffu, ss, m);
    __shared__ float sw[8];
    if ((c & 31) == 0) sw[c >> 5] = ss;
    __syncthreads();
    float tot = 0.f;
#pragma unroll
    for (int i = 0; i < 8; i++) tot += sw[i];
    float sc = rsqrtf(tot / (float)DM + 1e-5f);
    g_fus[bi * DM + c] = r * sc * w[c];
}

__global__ void heads_kernel(const float* __restrict__ bw1, const float* __restrict__ bb1,
                             const float* __restrict__ bw2, const float* __restrict__ bb2,
                             const float* __restrict__ pw1, const float* __restrict__ pb1,
                             const float* __restrict__ pw2, const float* __restrict__ pb2,
                             float* __restrict__ out) {
    int h = blockIdx.x;
    int b = blockIdx.y;
    int tid = threadIdx.x;
    __shared__ float sin_[DM];
    __shared__ float hidv[DM];
    sin_[tid] = g_fus[(b * 5 + h) * DM + tid];
    __syncthreads();

    const float *w1, *b1, *w2, *b2;
    int nout; bool sig;
    if (h == 0) { w1 = bw1; b1 = bb1; w2 = bw2; b2 = bb2; nout = 3; sig = false; }
    else {
        int i = h - 1;
        w1 = pw1 + (long)i * DM * DM; b1 = pb1 + i * DM;
        w2 = pw2 + i * 2 * DM;        b2 = pb2 + i * 2;
        nout = 2; sig = true;
    }
    float acc = b1[tid];
    for (int k = 0; k < DM; k++) acc = fmaf(sin_[k], w1[(long)tid * DM + k], acc);
    hidv[tid] = fmaxf(acc, 0.f);
    __syncthreads();

    int w = tid >> 5, lane = tid & 31;
    if (w < nout) {
        float a = 0.f;
        for (int k = lane; k < DM; k += 32) a += hidv[k] * w2[w * DM + k];
#pragma unroll
        for (int m = 16; m; m >>= 1) a += __shfl_xor_sync(0xffffffffu, a, m);
        if (lane == 0) {
            float v = a + b2[w];
            if (sig) v = 1.f / (1.f + __expf(-v));
            int o = (h == 0) ? (b * 11 + w) : (b * 11 + 3 + (h - 1) * 2 + w);
            out[o] = v;
        }
    }
}

// ---------------- host side ----------------
extern "C" void kernel_launch(void* const* d_in, const int* in_sizes, int n_in,
                              void* d_out, int out_size) {
    (void)in_sizes; (void)n_in; (void)out_size;
    const float* x        = (const float*)d_in[0];
    const float* patch_w  = (const float*)d_in[1];
    const float* patch_b  = (const float*)d_in[2];
    const float* pos      = (const float*)d_in[3];
    const float* temp     = (const float*)d_in[4];
    const float* in_proj  = (const float*)d_in[5];
    const float* convf_w  = (const float*)d_in[6];
    const float* convf_b  = (const float*)d_in[7];
    const float* xprojf   = (const float*)d_in[8];
    const float* dtf_w    = (const float*)d_in[9];
    const float* dtf_b    = (const float*)d_in[10];
    const float* A_logf   = (const float*)d_in[11];
    const float* Dsf      = (const float*)d_in[12];
    const float* convb_w  = (const float*)d_in[13];
    const float* convb_b  = (const float*)d_in[14];
    const float* xprojb   = (const float*)d_in[15];
    const float* dtb_w    = (const float*)d_in[16];
    const float* dtb_b    = (const float*)d_in[17];
    const float* A_logb   = (const float*)d_in[18];
    const float* Dsb      = (const float*)d_in[19];
    const float* out_proj = (const float*)d_in[20];
    const float* norm_w   = (const float*)d_in[21];
    const float* normf_w  = (const float*)d_in[22];
    const float* bbox_w1  = (const float*)d_in[23];
    const float* bbox_b1  = (const float*)d_in[24];
    const float* bbox_w2  = (const float*)d_in[25];
    const float* bbox_b2  = (const float*)d_in[26];
    const float* pix_w1   = (const float*)d_in[27];
    const float* pix_b1   = (const float*)d_in[28];
    const float* pix_w2   = (const float*)d_in[29];
    const float* pix_b2   = (const float*)d_in[30];
    float* out = (float*)d_out;

    float *p_im2col, *p_hidden, *p_hnorm, *p_xz, *p_xs, *p_dbl, *p_dt, *p_y;
    cudaGetSymbolAddress((void**)&p_im2col, g_im2col);
    cudaGetSymbolAddress((void**)&p_hidden, g_hidden);
    cudaGetSymbolAddress((void**)&p_hnorm,  g_hnorm);
    cudaGetSymbolAddress((void**)&p_xz,     g_xz);
    cudaGetSymbolAddress((void**)&p_xs,     g_xs);
    cudaGetSymbolAddress((void**)&p_dbl,    g_dbl);
    cudaGetSymbolAddress((void**)&p_dt,     g_dt);
    cudaGetSymbolAddress((void**)&p_y,      g_y);

    const int GY = (NT + TBM - 1) / TBM;   // 25

    prep_A_kernel<<<(NDEPTH * DI * DSTATE + 255) / 256, 256>>>(A_logf, A_logb);
    im2col_kernel<<<(NT * KPATCH + 255) / 256, 256>>>(x);

    // patch embed: N=256, K=768, split-K 2, atomic, EPI=2
    mma_gemm_kernel<2, true, false, false><<<dim3(4, GY, 2), 128>>>(
        p_im2col, nullptr, KPATCH, patch_w, nullptr, p_hidden, DM,
        NT, DM, KPATCH, 2, patch_b, nullptr, pos, temp, 0, 0);

    for (int i = 0; i < NDEPTH; i++) {
        addnorm_kernel<<<NT / 4, 128>>>(norm_w + i * DM, i == 0);
        // in_proj: N=1024, K=256
        mma_gemm_kernel<0, false, false, false><<<dim3(16, GY, 1), 128>>>(
            p_hnorm, nullptr, DM, in_proj + (long)i * 2 * DI * DM, nullptr,
            p_xz, 2 * DI, NT, 2 * DI, DM, 1, nullptr, nullptr, nullptr, nullptr, 0, 0);
        // conv + silu + transpose (fwd, bwd, z-gate)
        conv_kernel<<<dim3((LSEQ + CT - 1) / CT, DI / CD, 3 * BB), 256>>>(
            convf_w + (long)i * DI * 4, convf_b + i * DI,
            convb_w + (long)i * DI * 4, convb_b + i * DI);
        // xproj: A = xs_T (TRANSA), N=48, K=512, dirs 2, split-K 2, atomic
        mma_gemm_kernel<0, true, true, false><<<dim3(1, GY, 4), 128>>>(
            p_xs, nullptr, NT, xprojf + (long)i * 48 * DI, xprojb + (long)i * 48 * DI,
            p_dbl, 48, NT, 48, DI, 2, nullptr, nullptr, nullptr, nullptr,
            (long)DI * NT, (long)NT * 48);
        // dt: N=512, K=16, dirs 2, softplus, TRANSC -> dt_T
        mma_gemm_kernel<1, false, false, true><<<dim3(8, GY, 2), 128>>>(
            p_dbl, nullptr, 48, dtf_w + (long)i * DI * DTR, dtb_w + (long)i * DI * DTR,
            p_dt, NT, NT, DI, DTR, 1, dtf_b + i * DI, dtb_b + i * DI, nullptr, nullptr,
            (long)NT * 48, (long)DI * NT);
        scan_pass1_kernel<<<dim3(64, NCHUNK, 2), 256>>>(i);
        scan_pass2_kernel<<<dim3(64, NCHUNK, 2), 256>>>(i, Dsf + i * DI, Dsb + i * DI);
        // out_proj: A = y_T fwd + bwd (TRANSA), N=256, K=512, split-K 2, atomic
        mma_gemm_kernel<0, true, true, false><<<dim3(4, GY, 2), 128>>>(
            p_y, p_y + (long)DI * NT, NT, out_proj + (long)i * DM * DI, nullptr,
            p_hidden, DM, NT, DM, DI, 2, nullptr, nullptr, nullptr, nullptr, 0, 0);
    }

    finalnorm_kernel<<<BB * 5, 256>>>(normf_w);
    heads_kernel<<<dim3(5, BB), 256>>>(bbox_w1, bbox_b1, bbox_w2, bbox_b2,
                                       pix_w1, pix_b1, pix_w2, pix_b2, out);
}

// round 12
// speedup vs baseline: 2.0407x; 1.0718x over previous
#include <cuda_runtime.h>
#include <math.h>
#include <stdint.h>

#define BB      2
#define FRAMES  4
#define LSEQ    784
#define NT      1568
#define DM      256
#define DI      512
#define DSTATE  16
#define DTR     16
#define NDEPTH  12
#define NPATCH  196
#define KPATCH  768
#define NCHUNK  7
#define CLEN    112
#define NGRP    (2 * BB * DI * DSTATE)

// ---------------- scratch ----------------
__device__ float g_im2col[NT * KPATCH];
__device__ float g_hidden[NT * DM];
__device__ float g_resid [NT * DM];
__device__ float g_scale [NT];
__device__ float g_xz    [NT * 2 * DI];
__device__ float g_xs    [2 * DI * NT];   // TRANSPOSED: [dir][d][b*784+t]
__device__ float g_gz    [DI * NT];       // TRANSPOSED silu(z)
__device__ float g_dbl   [2 * NT * 48];
__device__ float g_dt    [2 * DI * NT];   // TRANSPOSED
__device__ float g_y     [2 * DI * NT];   // TRANSPOSED
__device__ float g_A     [2 * NDEPTH * DI * DSTATE];
__device__ float g_P     [NCHUNK][NGRP];
__device__ float g_q     [NCHUNK][NGRP];

static __device__ __forceinline__ float siluf(float x) {
    return x / (1.f + __expf(-x));
}
static __device__ __forceinline__ float softplusf(float x) {
    return (x > 20.f) ? x : log1pf(__expf(x));
}
static __device__ __forceinline__ uint32_t f2tf32(float x) {
    uint32_t r;
    asm("cvt.rna.tf32.f32 %0, %1;" : "=r"(r) : "f"(x));
    return r;
}
static __device__ __forceinline__ void mma_tf32(float* d, const uint32_t* a, const uint32_t* b) {
    asm volatile(
        "mma.sync.aligned.m16n8k8.row.col.f32.tf32.tf32.f32 "
        "{%0,%1,%2,%3}, {%4,%5,%6,%7}, {%8,%9}, {%0,%1,%2,%3};"
        : "+f"(d[0]), "+f"(d[1]), "+f"(d[2]), "+f"(d[3])
        : "r"(a[0]), "r"(a[1]), "r"(a[2]), "r"(a[3]), "r"(b[0]), "r"(b[1]));
}

// im2col + zero g_hidden + prep A (folded)
__global__ void im2col_kernel(const float* __restrict__ x,
                              const float* __restrict__ Af,
                              const float* __restrict__ Ab) {
    int e = blockIdx.x * blockDim.x + threadIdx.x;
    if (e >= NT * KPATCH) return;
    if (e < NT * DM) g_hidden[e] = 0.f;
    const int NA = NDEPTH * DI * DSTATE;
    if (e < NA) {
        g_A[e]      = -expf(Af[e]);
        g_A[NA + e] = -expf(Ab[e]);
    }
    int n = e / KPATCH, k = e % KPATCH;
    int b = n / LSEQ, tl = n % LSEQ;
    int t = tl / NPATCH, p = tl % NPATCH;
    int ph = p / 14, pw = p % 14;
    int ci = k / 256, rem = k % 256;
    int ii = rem / 16, jj = rem % 16;
    long off = (((long)(b * 3 + ci) * FRAMES + t) * 224 + (ph * 16 + ii)) * 224 + (pw * 16 + jj);
    g_im2col[e] = x[off];
}

// ---------------- TF32 tensor-core GEMM, 64x64 tile, 4 warps ------------------
// C[M,N] = (A [+A2]) @ W^T ; W is N x K row-major. z = dir*SK + ks.
// TRANSA: A col-major A[k*lda + row]. TRANSC: C written transposed, smem-staged.
// ANORM: A element scaled by g_scale[row]*nw[k] (fused rmsnorm for in_proj).
// EPI: 0 none, 1 softplus(+bias), 2 patch epilogue (ks==0 only).
#define TBM  64
#define TBN  64
#define TBK  16
#define TBKP 20
template <int EPI, bool ATOMIC, bool TRANSA, bool TRANSC, bool ANORM>
__global__ void __launch_bounds__(128)
mma_gemm_kernel(const float* __restrict__ A, const float* __restrict__ A2, int lda,
                const float* __restrict__ W, const float* __restrict__ Wb,
                float* __restrict__ C, int ldc,
                int M, int N, int K, int SK,
                const float* __restrict__ bias, const float* __restrict__ biasb,
                const float* __restrict__ pos, const float* __restrict__ temp,
                long strideA, long strideC,
                const float* __restrict__ nw) {
    __shared__ uint32_t As[2][TBM][TBKP];
    __shared__ uint32_t Bs[2][TBN][TBKP];

    int z = blockIdx.z;
    int dir = z / SK, ks = z - dir * SK;
    if (dir) { A += strideA; C += strideC; W = Wb; bias = biasb; if (A2) A2 += strideA; }
    int Kc = K / SK;
    int kbase = ks * Kc;
    int nk = Kc / TBK;

    int tid = threadIdx.x;
    int lane = tid & 31;
    int wid = tid >> 5;
    int wm = wid >> 1, wn = wid & 1;
    int qr = lane >> 2, qc = lane & 3;

    int rowBase = blockIdx.y * TBM;
    int colBase = blockIdx.x * TBN;

    float rowsc = 1.f;
    if (ANORM) {
        int r = rowBase + (tid >> 1);
        rowsc = (r < M) ? g_scale[r] : 0.f;
    }

    auto load_tile = [&](int k0, int buf) {
        if (TRANSA) {
#pragma unroll
            for (int it = 0; it < 2; it++) {
                int item = it * 128 + tid;
                int kk = item >> 4;
                int r4 = (item & 15) * 4;
                float4 v = make_float4(0.f, 0.f, 0.f, 0.f);
                int row = rowBase + r4;
                if (row < M) {
                    v = *(const float4*)&A[(long)(k0 + kk) * lda + row];
                    if (A2) {
                        float4 w = *(const float4*)&A2[(long)(k0 + kk) * lda + row];
                        v.x += w.x; v.y += w.y; v.z += w.z; v.w += w.w;
                    }
                }
                As[buf][r4 + 0][kk] = f2tf32(v.x);
                As[buf][r4 + 1][kk] = f2tf32(v.y);
                As[buf][r4 + 2][kk] = f2tf32(v.z);
                As[buf][r4 + 3][kk] = f2tf32(v.w);
            }
        } else {
            int lr = tid >> 1;
            int lc = (tid & 1) * 8;
            int r = rowBase + lr;
            float4 a0 = make_float4(0.f, 0.f, 0.f, 0.f);
            float4 a1 = make_float4(0.f, 0.f, 0.f, 0.f);
            if (r < M) {
                a0 = *(const float4*)&A[(long)r * lda + k0 + lc];
                a1 = *(const float4*)&A[(long)r * lda + k0 + lc + 4];
                if (A2) {
                    float4 w0 = *(const float4*)&A2[(long)r * lda + k0 + lc];
                    float4 w1 = *(const float4*)&A2[(long)r * lda + k0 + lc + 4];
                    a0.x += w0.x; a0.y += w0.y; a0.z += w0.z; a0.w += w0.w;
                    a1.x += w1.x; a1.y += w1.y; a1.z += w1.z; a1.w += w1.w;
                }
            }
            if (ANORM) {
                float4 n0 = *(const float4*)&nw[k0 + lc];
                float4 n1 = *(const float4*)&nw[k0 + lc + 4];
                a0.x *= rowsc * n0.x; a0.y *= rowsc * n0.y;
                a0.z *= rowsc * n0.z; a0.w *= rowsc * n0.w;
                a1.x *= rowsc * n1.x; a1.y *= rowsc * n1.y;
                a1.z *= rowsc * n1.z; a1.w *= rowsc * n1.w;
            }
            As[buf][lr][lc + 0] = f2tf32(a0.x); As[buf][lr][lc + 1] = f2tf32(a0.y);
            As[buf][lr][lc + 2] = f2tf32(a0.z); As[buf][lr][lc + 3] = f2tf32(a0.w);
            As[buf][lr][lc + 4] = f2tf32(a1.x); As[buf][lr][lc + 5] = f2tf32(a1.y);
            As[buf][lr][lc + 6] = f2tf32(a1.z); As[buf][lr][lc + 7] = f2tf32(a1.w);
        }
        {
            int lr = tid >> 1;
            int lc = (tid & 1) * 8;
            int col = colBase + lr;
            float4 b0 = make_float4(0.f, 0.f, 0.f, 0.f);
            float4 b1 = make_float4(0.f, 0.f, 0.f, 0.f);
            if (col < N) {
                b0 = *(const float4*)&W[(long)col * K + k0 + lc];
                b1 = *(const float4*)&W[(long)col * K + k0 + lc + 4];
            }
            Bs[buf][lr][lc + 0] = f2tf32(b0.x); Bs[buf][lr][lc + 1] = f2tf32(b0.y);
            Bs[buf][lr][lc + 2] = f2tf32(b0.z); Bs[buf][lr][lc + 3] = f2tf32(b0.w);
            Bs[buf][lr][lc + 4] = f2tf32(b1.x); Bs[buf][lr][lc + 5] = f2tf32(b1.y);
            Bs[buf][lr][lc + 6] = f2tf32(b1.z); Bs[buf][lr][lc + 7] = f2tf32(b1.w);
        }
    };

    float acc[2][4][4];
#pragma unroll
    for (int mi = 0; mi < 2; mi++)
#pragma unroll
        for (int ni = 0; ni < 4; ni++)
#pragma unroll
            for (int u = 0; u < 4; u++) acc[mi][ni][u] = 0.f;

    load_tile(kbase, 0);
    __syncthreads();

    for (int c = 0; c < nk; c++) {
        int cur = c & 1, nxt = cur ^ 1;
        if (c + 1 < nk) load_tile(kbase + (c + 1) * TBK, nxt);
#pragma unroll
        for (int c2 = 0; c2 < 2; c2++) {
            uint32_t af[2][4], bf[4][2];
#pragma unroll
            for (int mi = 0; mi < 2; mi++) {
                int r = wm * 32 + mi * 16 + qr;
                af[mi][0] = As[cur][r][c2 * 8 + qc];
                af[mi][1] = As[cur][r + 8][c2 * 8 + qc];
                af[mi][2] = As[cur][r][c2 * 8 + 4 + qc];
                af[mi][3] = As[cur][r + 8][c2 * 8 + 4 + qc];
            }
#pragma unroll
            for (int ni = 0; ni < 4; ni++) {
                int n = wn * 32 + ni * 8 + qr;
                bf[ni][0] = Bs[cur][n][c2 * 8 + qc];
                bf[ni][1] = Bs[cur][n][c2 * 8 + 4 + qc];
            }
#pragma unroll
            for (int mi = 0; mi < 2; mi++)
#pragma unroll
                for (int ni = 0; ni < 4; ni++)
                    mma_tf32(acc[mi][ni], af[mi], bf[ni]);
        }
        __syncthreads();
    }

    if (TRANSC) {
        __shared__ float stage[TBN][68];
#pragma unroll
        for (int mi = 0; mi < 2; mi++) {
#pragma unroll
            for (int ni = 0; ni < 4; ni++) {
                int r0 = wm * 32 + mi * 16 + qr;
                int c0 = wn * 32 + ni * 8 + 2 * qc;
#pragma unroll
                for (int u = 0; u < 4; u++) {
                    int rl = r0 + (u >= 2 ? 8 : 0);
                    int cl = c0 + (u & 1);
                    float v = acc[mi][ni][u];
                    if (EPI == 1) v = softplusf(v + bias[colBase + cl]);
                    stage[cl][rl] = v;
                }
            }
        }
        __syncthreads();
#pragma unroll
        for (int it = 0; it < 8; it++) {
            int item = it * 128 + tid;
            int col = item >> 4;
            int r = (item & 15) * 4;
            int row = rowBase + r;
            if (row < M) {
                float4 v = *(const float4*)&stage[col][r];
                *(float4*)&C[(long)(colBase + col) * ldc + row] = v;
            }
        }
    } else {
#pragma unroll
        for (int mi = 0; mi < 2; mi++) {
#pragma unroll
            for (int ni = 0; ni < 4; ni++) {
                int r0 = rowBase + wm * 32 + mi * 16 + qr;
                int c0 = colBase + wn * 32 + ni * 8 + 2 * qc;
#pragma unroll
                for (int u = 0; u < 4; u++) {
                    int row = r0 + (u >= 2 ? 8 : 0);
                    int col = c0 + (u & 1);
                    if (row >= M || col >= N) continue;
                    float v = acc[mi][ni][u];
                    if (EPI == 1) {
                        v = softplusf(v + bias[col]);
                    } else if (EPI == 2) {
                        if (ks == 0) {
                            int tl = row % LSEQ;
                            int t = tl / NPATCH, p = tl % NPATCH;
                            v += bias[col] + pos[p * DM + col] + temp[t * DM + col];
                        }
                    }
                    if (ATOMIC) atomicAdd(&C[(long)row * ldc + col], v);
                    else        C[(long)row * ldc + col] = v;
                }
            }
        }
    }
}

// ---------------- slim residual add + rms scale -------------------------------
// resid += hidden (write resid), scale[row] = rsqrt(mean(resid^2)+eps).
__global__ void __launch_bounds__(128)
addnorm_kernel(int first) {
    int wid = threadIdx.x >> 5, lane = threadIdx.x & 31;
    int n = blockIdx.x * 4 + wid;

    const float4* hp = (const float4*)(g_hidden + (long)n * DM);
    float4* rp = (float4*)(g_resid + (long)n * DM);
    float4 h0 = hp[lane], h1 = hp[32 + lane];
    if (!first) {
        float4 r0 = rp[lane], r1 = rp[32 + lane];
        h0.x += r0.x; h0.y += r0.y; h0.z += r0.z; h0.w += r0.w;
        h1.x += r1.x; h1.y += r1.y; h1.z += r1.z; h1.w += r1.w;
    }
    rp[lane] = h0; rp[32 + lane] = h1;
    float ss = h0.x*h0.x + h0.y*h0.y + h0.z*h0.z + h0.w*h0.w
             + h1.x*h1.x + h1.y*h1.y + h1.z*h1.z + h1.w*h1.w;
#pragma unroll
    for (int m = 16; m; m >>= 1) ss += __shfl_xor_sync(0xffffffffu, ss, m);
    if (lane == 0) g_scale[n] = rsqrtf(ss / (float)DM + 1e-5f);
}

// ---------------- conv + silu + transpose  (and z-gate transpose) -------------
// Also zeroes g_hidden (for out_proj atomics) and g_dbl (for xproj atomics).
#define CT 64
#define CD 32
__global__ void __launch_bounds__(256)
conv_kernel(const float* __restrict__ cwf, const float* __restrict__ cbf,
            const float* __restrict__ cwb, const float* __restrict__ cbb) {
    // zeroing: grid has 13*16*6 = 1248 blocks * 256 threads = 319488 threads
    {
        int nb = gridDim.x * gridDim.y;   // blocks per z-slice: 13*16 = 208
        int bid = (blockIdx.z * gridDim.y + blockIdx.y) * gridDim.x + blockIdx.x;
        int gid = bid * 256 + threadIdx.x;
        (void)nb;
        const int NH4 = NT * DM / 4;          // 100352
        const int ND4 = 2 * NT * 48 / 4;      // 37632
        if (gid < NH4) ((float4*)g_hidden)[gid] = make_float4(0.f, 0.f, 0.f, 0.f);
        else if (gid < NH4 + ND4) ((float4*)g_dbl)[gid - NH4] = make_float4(0.f, 0.f, 0.f, 0.f);
    }
    __shared__ float tile[CT + 3][CD + 1];
    int mode = blockIdx.z / BB;
    int b = blockIdx.z % BB;
    int t0 = blockIdx.x * CT;
    int d0 = blockIdx.y * CD;
    int tid = threadIdx.x;
    int colbase = (mode == 2 ? DI : 0) + d0;

    int rr = tid >> 3, cc = (tid & 7) * 4;
#pragma unroll
    for (int it = 0; it < 3; it++) {
        int r = it * 32 + rr;
        if (r < CT + 3) {
            int ss = t0 - 3 + r;
            float4 v = make_float4(0.f, 0.f, 0.f, 0.f);
            if (ss >= 0 && ss < LSEQ) {
                int src = (mode == 1) ? (LSEQ - 1 - ss) : ss;
                v = *(const float4*)&g_xz[(long)(b * LSEQ + src) * (2 * DI) + colbase + cc];
            }
            tile[r][cc + 0] = v.x; tile[r][cc + 1] = v.y;
            tile[r][cc + 2] = v.z; tile[r][cc + 3] = v.w;
        }
    }
    __syncthreads();

    int tl = tid & 63, dg = tid >> 6;
    int tt = t0 + tl;
    if (tt >= LSEQ) return;
    if (mode == 2) {
#pragma unroll
        for (int i = 0; i < 8; i++) {
            int dl = dg * 8 + i;
            float v = siluf(tile[tl + 3][dl]);
            g_gz[(long)(d0 + dl) * NT + b * LSEQ + tt] = v;
        }
    } else {
        const float* cw = mode ? cwb : cwf;
        const float* cb = mode ? cbb : cbf;
#pragma unroll
        for (int i = 0; i < 8; i++) {
            int dl = dg * 8 + i;
            int d = d0 + dl;
            float acc = cb[d];
#pragma unroll
            for (int k = 0; k < 4; k++)
                acc = fmaf(tile[tl + k][dl], cw[d * 4 + k], acc);
            g_xs[((long)mode * DI + d) * NT + b * LSEQ + tt] = siluf(acc);
        }
    }
}

// ---------------- chunked SSM scan (two-pass, transposed inputs) --------------
__global__ void scan_pass1_kernel(int layer) {
    int dir = blockIdx.z;
    int c = blockIdx.y;
    int tid = threadIdx.x;
    int grp = tid >> 4, s = tid & 15;
    int ch = blockIdx.x * 16 + grp;
    int b = ch >> 9, d = ch & (DI - 1);
    int e = ((dir * BB + b) * DI + d) * DSTATE + s;

    const float A_ds = g_A[(dir * NDEPTH + layer) * DI * DSTATE + d * DSTATE + s];
    long base = ((long)dir * DI + d) * NT + b * LSEQ;
    const float* dtp = g_dt + base;
    const float* xsp = g_xs + base;
    const float* dblp = g_dbl + ((long)dir * NT + b * LSEQ) * 48;

    float P = 1.f, q = 0.f;
    int t0 = c * CLEN;
    for (int tb = 0; tb < CLEN; tb += 16) {
        int tt = t0 + tb;
        float dtv = dtp[tt + s];
        float uv  = xsp[tt + s];
#pragma unroll
        for (int j = 0; j < 16; j++) {
            float dt = __shfl_sync(0xffffffffu, dtv, j, 16);
            float u  = __shfl_sync(0xffffffffu, uv,  j, 16);
            float Bv = dblp[(tt + j) * 48 + 16 + s];
            float a = __expf(dt * A_ds);
            P *= a;
            q = fmaf(a, q, (dt * u) * Bv);
        }
    }
    g_P[c][e] = P;
    g_q[c][e] = q;
}

__global__ void scan_pass2_kernel(int layer, const float* __restrict__ Dsf,
                                  const float* __restrict__ Dsb) {
    int dir = blockIdx.z;
    int c = blockIdx.y;
    int tid = threadIdx.x;
    int grp = tid >> 4, s = tid & 15;
    int ch = blockIdx.x * 16 + grp;
    int b = ch >> 9, d = ch & (DI - 1);
    int e = ((dir * BB + b) * DI + d) * DSTATE + s;

    const float A_ds = g_A[(dir * NDEPTH + layer) * DI * DSTATE + d * DSTATE + s];
    const float Dd = (dir ? Dsb : Dsf)[d];
    long base = ((long)dir * DI + d) * NT + b * LSEQ;
    const float* dtp = g_dt + base;
    const float* xsp = g_xs + base;
    const float* dblp = g_dbl + ((long)dir * NT + b * LSEQ) * 48;
    const float* gzp = g_gz + (long)d * NT + b * LSEQ;
    float* yp = g_y + base;

    float h = 0.f;
    for (int cc = 0; cc < c; cc++) h = fmaf(g_P[cc][e], h, g_q[cc][e]);

    int t0 = c * CLEN;
    float yb0 = 0.f, yb1 = 0.f, yb2 = 0.f;
    for (int tb = 0; tb < CLEN; tb += 16) {
        int tt = t0 + tb;
        float dtv = dtp[tt + s];
        float uv  = xsp[tt + s];
#pragma unroll
        for (int j = 0; j < 16; j++) {
            int ss = tt + j;
            float dt = __shfl_sync(0xffffffffu, dtv, j, 16);
            float u  = __shfl_sync(0xffffffffu, uv,  j, 16);
            float Bv = dblp[ss * 48 + 16 + s];
            float Cv = dblp[ss * 48 + 32 + s];
            float a = __expf(dt * A_ds);
            h = fmaf(a, h, (dt * u) * Bv);
            float p = h * Cv;
            p += __shfl_xor_sync(0xffffffffu, p, 8);
            p += __shfl_xor_sync(0xffffffffu, p, 4);
            p += __shfl_xor_sync(0xffffffffu, p, 2);
            p += __shfl_xor_sync(0xffffffffu, p, 1);
            if (s == 0) {
                int orig = dir ? (LSEQ - 1 - ss) : ss;
                float val = (p + Dd * u) * gzp[orig];
                if ((j & 3) == 0) yb0 = val;
                else if ((j & 3) == 1) yb1 = val;
                else if ((j & 3) == 2) yb2 = val;
                else {
                    float4 o = dir ? make_float4(val, yb2, yb1, yb0)
                                   : make_float4(yb0, yb1, yb2, val);
                    int addr = dir ? (LSEQ - 1 - ss) : (ss - 3);
                    *(float4*)&yp[addr] = o;
                }
            }
        }
    }
}

// ---------------- heads (with fused final rmsnorm) ----------------------------
__global__ void heads_kernel(const float* __restrict__ normf_w,
                             const float* __restrict__ bw1, const float* __restrict__ bb1,
                             const float* __restrict__ bw2, const float* __restrict__ bb2,
                             const float* __restrict__ pw1, const float* __restrict__ pb1,
                             const float* __restrict__ pw2, const float* __restrict__ pb2,
                             float* __restrict__ out) {
    int h = blockIdx.x;                 // 0..4 = token index
    int b = blockIdx.y;
    int tid = threadIdx.x;
    __shared__ float sin_[DM];
    __shared__ float hidv[DM];
    __shared__ float sw[8];

    // fused finalnorm on token row n
    int n = b * LSEQ + h;
    float r = g_resid[n * DM + tid] + g_hidden[n * DM + tid];
    float ss = r * r;
#pragma unroll
    for (int m = 16; m; m >>= 1) ss += __shfl_xor_sync(0xffffffffu, ss, m);
    if ((tid & 31) == 0) sw[tid >> 5] = ss;
    __syncthreads();
    float tot = 0.f;
#pragma unroll
    for (int i = 0; i < 8; i++) tot += sw[i];
    float sc = rsqrtf(tot / (float)DM + 1e-5f);
    sin_[tid] = r * sc * normf_w[tid];
    __syncthreads();

    const float *w1, *b1, *w2, *b2;
    int nout; bool sig;
    if (h == 0) { w1 = bw1; b1 = bb1; w2 = bw2; b2 = bb2; nout = 3; sig = false; }
    else {
        int i = h - 1;
        w1 = pw1 + (long)i * DM * DM; b1 = pb1 + i * DM;
        w2 = pw2 + i * 2 * DM;        b2 = pb2 + i * 2;
        nout = 2; sig = true;
    }
    float acc = b1[tid];
    for (int k = 0; k < DM; k++) acc = fmaf(sin_[k], w1[(long)tid * DM + k], acc);
    hidv[tid] = fmaxf(acc, 0.f);
    __syncthreads();

    int w = tid >> 5, lane = tid & 31;
    if (w < nout) {
        float a = 0.f;
        for (int k = lane; k < DM; k += 32) a += hidv[k] * w2[w * DM + k];
#pragma unroll
        for (int m = 16; m; m >>= 1) a += __shfl_xor_sync(0xffffffffu, a, m);
        if (lane == 0) {
            float v = a + b2[w];
            if (sig) v = 1.f / (1.f + __expf(-v));
            int o = (h == 0) ? (b * 11 + w) : (b * 11 + 3 + (h - 1) * 2 + w);
            out[o] = v;
        }
    }
}

// ---------------- host side ----------------
extern "C" void kernel_launch(void* const* d_in, const int* in_sizes, int n_in,
                              void* d_out, int out_size) {
    (void)in_sizes; (void)n_in; (void)out_size;
    const float* x        = (const float*)d_in[0];
    const float* patch_w  = (const float*)d_in[1];
    const float* patch_b  = (const float*)d_in[2];
    const float* pos      = (const float*)d_in[3];
    const float* temp     = (const float*)d_in[4];
    const float* in_proj  = (const float*)d_in[5];
    const float* convf_w  = (const float*)d_in[6];
    const float* convf_b  = (const float*)d_in[7];
    const float* xprojf   = (const float*)d_in[8];
    const float* dtf_w    = (const float*)d_in[9];
    const float* dtf_b    = (const float*)d_in[10];
    const float* A_logf   = (const float*)d_in[11];
    const float* Dsf      = (const float*)d_in[12];
    const float* convb_w  = (const float*)d_in[13];
    const float* convb_b  = (const float*)d_in[14];
    const float* xprojb   = (const float*)d_in[15];
    const float* dtb_w    = (const float*)d_in[16];
    const float* dtb_b    = (const float*)d_in[17];
    const float* A_logb   = (const float*)d_in[18];
    const float* Dsb      = (const float*)d_in[19];
    const float* out_proj = (const float*)d_in[20];
    const float* norm_w   = (const float*)d_in[21];
    const float* normf_w  = (const float*)d_in[22];
    const float* bbox_w1  = (const float*)d_in[23];
    const float* bbox_b1  = (const float*)d_in[24];
    const float* bbox_w2  = (const float*)d_in[25];
    const float* bbox_b2  = (const float*)d_in[26];
    const float* pix_w1   = (const float*)d_in[27];
    const float* pix_b1   = (const float*)d_in[28];
    const float* pix_w2   = (const float*)d_in[29];
    const float* pix_b2   = (const float*)d_in[30];
    float* out = (float*)d_out;

    float *p_im2col, *p_hidden, *p_resid, *p_xz, *p_xs, *p_dbl, *p_dt, *p_y;
    cudaGetSymbolAddress((void**)&p_im2col, g_im2col);
    cudaGetSymbolAddress((void**)&p_hidden, g_hidden);
    cudaGetSymbolAddress((void**)&p_resid,  g_resid);
    cudaGetSymbolAddress((void**)&p_xz,     g_xz);
    cudaGetSymbolAddress((void**)&p_xs,     g_xs);
    cudaGetSymbolAddress((void**)&p_dbl,    g_dbl);
    cudaGetSymbolAddress((void**)&p_dt,     g_dt);
    cudaGetSymbolAddress((void**)&p_y,      g_y);

    const int GY = (NT + TBM - 1) / TBM;   // 25

    im2col_kernel<<<(NT * KPATCH + 255) / 256, 256>>>(x, A_logf, A_logb);

    // patch embed: N=256, K=768, split-K 2, atomic, EPI=2
    mma_gemm_kernel<2, true, false, false, false><<<dim3(4, GY, 2), 128>>>(
        p_im2col, nullptr, KPATCH, patch_w, nullptr, p_hidden, DM,
        NT, DM, KPATCH, 2, patch_b, nullptr, pos, temp, 0, 0, nullptr);

    for (int i = 0; i < NDEPTH; i++) {
        addnorm_kernel<<<NT / 4, 128>>>(i == 0);
        // in_proj: A = resid (ANORM: * scale[row] * norm_w[k]), N=1024, K=256
        mma_gemm_kernel<0, false, false, false, true><<<dim3(16, GY, 1), 128>>>(
            p_resid, nullptr, DM, in_proj + (long)i * 2 * DI * DM, nullptr,
            p_xz, 2 * DI, NT, 2 * DI, DM, 1, nullptr, nullptr, nullptr, nullptr, 0, 0,
            norm_w + i * DM);
        // conv + silu + transpose (fwd, bwd, z-gate); also zeroes hidden & dbl
        conv_kernel<<<dim3((LSEQ + CT - 1) / CT, DI / CD, 3 * BB), 256>>>(
            convf_w + (long)i * DI * 4, convf_b + i * DI,
            convb_w + (long)i * DI * 4, convb_b + i * DI);
        // xproj: A = xs_T (TRANSA), N=48, K=512, dirs 2, split-K 2, atomic
        mma_gemm_kernel<0, true, true, false, false><<<dim3(1, GY, 4), 128>>>(
            p_xs, nullptr, NT, xprojf + (long)i * 48 * DI, xprojb + (long)i * 48 * DI,
            p_dbl, 48, NT, 48, DI, 2, nullptr, nullptr, nullptr, nullptr,
            (long)DI * NT, (long)NT * 48, nullptr);
        // dt: N=512, K=16, dirs 2, softplus, TRANSC -> dt_T
        mma_gemm_kernel<1, false, false, true, false><<<dim3(8, GY, 2), 128>>>(
            p_dbl, nullptr, 48, dtf_w + (long)i * DI * DTR, dtb_w + (long)i * DI * DTR,
            p_dt, NT, NT, DI, DTR, 1, dtf_b + i * DI, dtb_b + i * DI, nullptr, nullptr,
            (long)NT * 48, (long)DI * NT, nullptr);
        scan_pass1_kernel<<<dim3(64, NCHUNK, 2), 256>>>(i);
        scan_pass2_kernel<<<dim3(64, NCHUNK, 2), 256>>>(i, Dsf + i * DI, Dsb + i * DI);
        // out_proj: A = y_T fwd + bwd (TRANSA), N=256, K=512, split-K 2, atomic
        mma_gemm_kernel<0, true, true, false, false><<<dim3(4, GY, 2), 128>>>(
            p_y, p_y + (long)DI * NT, NT, out_proj + (long)i * DM * DI, nullptr,
            p_hidden, DM, NT, DM, DI, 2, nullptr, nullptr, nullptr, nullptr, 0, 0, nullptr);
    }

    heads_kernel<<<dim3(5, BB), 256>>>(normf_w, bbox_w1, bbox_b1, bbox_w2, bbox_b2,
                                       pix_w1, pix_b1, pix_w2, pix_b2, out);
}

// round 13
// speedup vs baseline: 2.4354x; 1.1934x over previous
#include <cuda_runtime.h>
#include <math.h>
#include <stdint.h>

#define BB      2
#define FRAMES  4
#define LSEQ    784
#define NT      1568
#define DM      256
#define DI      512
#define DSTATE  16
#define DTR     16
#define NDEPTH  12
#define NPATCH  196
#define KPATCH  768
#define NCHUNK  7
#define CLEN    112
#define NGRP    (2 * BB * DI * DSTATE)

// ---------------- scratch ----------------
__device__ float g_im2col[NT * KPATCH];
__device__ float g_hidden[NT * DM];
__device__ float g_resid [NT * DM];
__device__ float g_scale [NT];
__device__ float g_xz    [NT * 2 * DI];
__device__ float g_xs    [2 * DI * NT];   // TRANSPOSED: [dir][d][b*784+t]
__device__ float g_gz    [DI * NT];       // TRANSPOSED silu(z)
__device__ float g_dbl   [2 * NT * 48];
__device__ float g_dt    [2 * DI * NT];   // TRANSPOSED
__device__ float g_y     [2 * DI * NT];   // TRANSPOSED
__device__ float g_A     [2 * NDEPTH * DI * DSTATE];
__device__ float g_P     [NCHUNK][NGRP];
__device__ float g_q     [NCHUNK][NGRP];

static __device__ __forceinline__ float siluf(float x) {
    return x / (1.f + __expf(-x));
}
static __device__ __forceinline__ float softplusf(float x) {
    return (x > 20.f) ? x : log1pf(__expf(x));
}
static __device__ __forceinline__ uint32_t f2tf32(float x) {
    uint32_t r;
    asm("cvt.rna.tf32.f32 %0, %1;" : "=r"(r) : "f"(x));
    return r;
}
static __device__ __forceinline__ void mma_tf32(float* d, const uint32_t* a, const uint32_t* b) {
    asm volatile(
        "mma.sync.aligned.m16n8k8.row.col.f32.tf32.tf32.f32 "
        "{%0,%1,%2,%3}, {%4,%5,%6,%7}, {%8,%9}, {%0,%1,%2,%3};"
        : "+f"(d[0]), "+f"(d[1]), "+f"(d[2]), "+f"(d[3])
        : "r"(a[0]), "r"(a[1]), "r"(a[2]), "r"(a[3]), "r"(b[0]), "r"(b[1]));
}

// im2col + zero g_hidden + prep A (folded)
__global__ void im2col_kernel(const float* __restrict__ x,
                              const float* __restrict__ Af,
                              const float* __restrict__ Ab) {
    int e = blockIdx.x * blockDim.x + threadIdx.x;
    if (e >= NT * KPATCH) return;
    if (e < NT * DM) g_hidden[e] = 0.f;
    const int NA = NDEPTH * DI * DSTATE;
    if (e < NA) {
        g_A[e]      = -expf(Af[e]);
        g_A[NA + e] = -expf(Ab[e]);
    }
    int n = e / KPATCH, k = e % KPATCH;
    int b = n / LSEQ, tl = n % LSEQ;
    int t = tl / NPATCH, p = tl % NPATCH;
    int ph = p / 14, pw = p % 14;
    int ci = k / 256, rem = k % 256;
    int ii = rem / 16, jj = rem % 16;
    long off = (((long)(b * 3 + ci) * FRAMES + t) * 224 + (ph * 16 + ii)) * 224 + (pw * 16 + jj);
    g_im2col[e] = x[off];
}

// ---------------- TF32 tensor-core GEMM, 64x64 tile, 4 warps ------------------
// C[M,N] = (A [+A2]) @ W^T ; W is N x K row-major. z = dir*SK + ks.
// TRANSA: A col-major A[k*lda + row]. TRANSC: C written transposed, smem-staged.
// ANORM: A element scaled by g_scale[row]*nw[k] (fused rmsnorm for in_proj).
// EPI: 0 none, 1 softplus(+bias), 2 patch epilogue (ks==0 only).
#define TBM  64
#define TBN  64
#define TBK  16
#define TBKP 20
template <int EPI, bool ATOMIC, bool TRANSA, bool TRANSC, bool ANORM>
__global__ void __launch_bounds__(128)
mma_gemm_kernel(const float* __restrict__ A, const float* __restrict__ A2, int lda,
                const float* __restrict__ W, const float* __restrict__ Wb,
                float* __restrict__ C, int ldc,
                int M, int N, int K, int SK,
                const float* __restrict__ bias, const float* __restrict__ biasb,
                const float* __restrict__ pos, const float* __restrict__ temp,
                long strideA, long strideC,
                const float* __restrict__ nw) {
    __shared__ uint32_t As[2][TBM][TBKP];
    __shared__ uint32_t Bs[2][TBN][TBKP];

    int z = blockIdx.z;
    int dir = z / SK, ks = z - dir * SK;
    if (dir) { A += strideA; C += strideC; W = Wb; bias = biasb; if (A2) A2 += strideA; }
    int Kc = K / SK;
    int kbase = ks * Kc;
    int nk = Kc / TBK;

    int tid = threadIdx.x;
    int lane = tid & 31;
    int wid = tid >> 5;
    int wm = wid >> 1, wn = wid & 1;
    int qr = lane >> 2, qc = lane & 3;

    int rowBase = blockIdx.y * TBM;
    int colBase = blockIdx.x * TBN;

    float rowsc = 1.f;
    if (ANORM) {
        int r = rowBase + (tid >> 1);
        rowsc = (r < M) ? g_scale[r] : 0.f;
    }

    auto load_tile = [&](int k0, int buf) {
        if (TRANSA) {
#pragma unroll
            for (int it = 0; it < 2; it++) {
                int item = it * 128 + tid;
                int kk = item >> 4;
                int r4 = (item & 15) * 4;
                float4 v = make_float4(0.f, 0.f, 0.f, 0.f);
                int row = rowBase + r4;
                if (row < M) {
                    v = *(const float4*)&A[(long)(k0 + kk) * lda + row];
                    if (A2) {
                        float4 w = *(const float4*)&A2[(long)(k0 + kk) * lda + row];
                        v.x += w.x; v.y += w.y; v.z += w.z; v.w += w.w;
                    }
                }
                As[buf][r4 + 0][kk] = f2tf32(v.x);
                As[buf][r4 + 1][kk] = f2tf32(v.y);
                As[buf][r4 + 2][kk] = f2tf32(v.z);
                As[buf][r4 + 3][kk] = f2tf32(v.w);
            }
        } else {
            int lr = tid >> 1;
            int lc = (tid & 1) * 8;
            int r = rowBase + lr;
            float4 a0 = make_float4(0.f, 0.f, 0.f, 0.f);
            float4 a1 = make_float4(0.f, 0.f, 0.f, 0.f);
            if (r < M) {
                a0 = *(const float4*)&A[(long)r * lda + k0 + lc];
                a1 = *(const float4*)&A[(long)r * lda + k0 + lc + 4];
                if (A2) {
                    float4 w0 = *(const float4*)&A2[(long)r * lda + k0 + lc];
                    float4 w1 = *(const float4*)&A2[(long)r * lda + k0 + lc + 4];
                    a0.x += w0.x; a0.y += w0.y; a0.z += w0.z; a0.w += w0.w;
                    a1.x += w1.x; a1.y += w1.y; a1.z += w1.z; a1.w += w1.w;
                }
            }
            if (ANORM) {
                float4 n0 = *(const float4*)&nw[k0 + lc];
                float4 n1 = *(const float4*)&nw[k0 + lc + 4];
                a0.x *= rowsc * n0.x; a0.y *= rowsc * n0.y;
                a0.z *= rowsc * n0.z; a0.w *= rowsc * n0.w;
                a1.x *= rowsc * n1.x; a1.y *= rowsc * n1.y;
                a1.z *= rowsc * n1.z; a1.w *= rowsc * n1.w;
            }
            As[buf][lr][lc + 0] = f2tf32(a0.x); As[buf][lr][lc + 1] = f2tf32(a0.y);
            As[buf][lr][lc + 2] = f2tf32(a0.z); As[buf][lr][lc + 3] = f2tf32(a0.w);
            As[buf][lr][lc + 4] = f2tf32(a1.x); As[buf][lr][lc + 5] = f2tf32(a1.y);
            As[buf][lr][lc + 6] = f2tf32(a1.z); As[buf][lr][lc + 7] = f2tf32(a1.w);
        }
        {
            int lr = tid >> 1;
            int lc = (tid & 1) * 8;
            int col = colBase + lr;
            float4 b0 = make_float4(0.f, 0.f, 0.f, 0.f);
            float4 b1 = make_float4(0.f, 0.f, 0.f, 0.f);
            if (col < N) {
                b0 = *(const float4*)&W[(long)col * K + k0 + lc];
                b1 = *(const float4*)&W[(long)col * K + k0 + lc + 4];
            }
            Bs[buf][lr][lc + 0] = f2tf32(b0.x); Bs[buf][lr][lc + 1] = f2tf32(b0.y);
            Bs[buf][lr][lc + 2] = f2tf32(b0.z); Bs[buf][lr][lc + 3] = f2tf32(b0.w);
            Bs[buf][lr][lc + 4] = f2tf32(b1.x); Bs[buf][lr][lc + 5] = f2tf32(b1.y);
            Bs[buf][lr][lc + 6] = f2tf32(b1.z); Bs[buf][lr][lc + 7] = f2tf32(b1.w);
        }
    };

    float acc[2][4][4];
#pragma unroll
    for (int mi = 0; mi < 2; mi++)
#pragma unroll
        for (int ni = 0; ni < 4; ni++)
#pragma unroll
            for (int u = 0; u < 4; u++) acc[mi][ni][u] = 0.f;

    load_tile(kbase, 0);
    __syncthreads();

    for (int c = 0; c < nk; c++) {
        int cur = c & 1, nxt = cur ^ 1;
        if (c + 1 < nk) load_tile(kbase + (c + 1) * TBK, nxt);
#pragma unroll
        for (int c2 = 0; c2 < 2; c2++) {
            uint32_t af[2][4], bf[4][2];
#pragma unroll
            for (int mi = 0; mi < 2; mi++) {
                int r = wm * 32 + mi * 16 + qr;
                af[mi][0] = As[cur][r][c2 * 8 + qc];
                af[mi][1] = As[cur][r + 8][c2 * 8 + qc];
                af[mi][2] = As[cur][r][c2 * 8 + 4 + qc];
                af[mi][3] = As[cur][r + 8][c2 * 8 + 4 + qc];
            }
#pragma unroll
            for (int ni = 0; ni < 4; ni++) {
                int n = wn * 32 + ni * 8 + qr;
                bf[ni][0] = Bs[cur][n][c2 * 8 + qc];
                bf[ni][1] = Bs[cur][n][c2 * 8 + 4 + qc];
            }
#pragma unroll
            for (int mi = 0; mi < 2; mi++)
#pragma unroll
                for (int ni = 0; ni < 4; ni++)
                    mma_tf32(acc[mi][ni], af[mi], bf[ni]);
        }
        __syncthreads();
    }

    if (TRANSC) {
        __shared__ float stage[TBN][68];
#pragma unroll
        for (int mi = 0; mi < 2; mi++) {
#pragma unroll
            for (int ni = 0; ni < 4; ni++) {
                int r0 = wm * 32 + mi * 16 + qr;
                int c0 = wn * 32 + ni * 8 + 2 * qc;
#pragma unroll
                for (int u = 0; u < 4; u++) {
                    int rl = r0 + (u >= 2 ? 8 : 0);
                    int cl = c0 + (u & 1);
                    float v = acc[mi][ni][u];
                    if (EPI == 1) v = softplusf(v + bias[colBase + cl]);
                    stage[cl][rl] = v;
                }
            }
        }
        __syncthreads();
#pragma unroll
        for (int it = 0; it < 8; it++) {
            int item = it * 128 + tid;
            int col = item >> 4;
            int r = (item & 15) * 4;
            int row = rowBase + r;
            if (row < M) {
                float4 v = *(const float4*)&stage[col][r];
                *(float4*)&C[(long)(colBase + col) * ldc + row] = v;
            }
        }
    } else {
#pragma unroll
        for (int mi = 0; mi < 2; mi++) {
#pragma unroll
            for (int ni = 0; ni < 4; ni++) {
                int r0 = rowBase + wm * 32 + mi * 16 + qr;
                int c0 = colBase + wn * 32 + ni * 8 + 2 * qc;
#pragma unroll
                for (int u = 0; u < 4; u++) {
                    int row = r0 + (u >= 2 ? 8 : 0);
                    int col = c0 + (u & 1);
                    if (row >= M || col >= N) continue;
                    float v = acc[mi][ni][u];
                    if (EPI == 1) {
                        v = softplusf(v + bias[col]);
                    } else if (EPI == 2) {
                        if (ks == 0) {
                            int tl = row % LSEQ;
                            int t = tl / NPATCH, p = tl % NPATCH;
                            v += bias[col] + pos[p * DM + col] + temp[t * DM + col];
                        }
                    }
                    if (ATOMIC) atomicAdd(&C[(long)row * ldc + col], v);
                    else        C[(long)row * ldc + col] = v;
                }
            }
        }
    }
}

// ---------------- slim residual add + rms scale + zero g_xz -------------------
// resid += hidden; scale[row] = rsqrt(mean(resid^2)+eps); zero g_xz (for
// split-K atomic in_proj): 50176 threads x 8 float4 = 401408 = NT*1024/4.
__global__ void __launch_bounds__(128)
addnorm_kernel(int first) {
    int wid = threadIdx.x >> 5, lane = threadIdx.x & 31;
    int n = blockIdx.x * 4 + wid;
    {
        int gt = blockIdx.x * 128 + threadIdx.x;
        float4* xzp = (float4*)g_xz;
        float4 zero = make_float4(0.f, 0.f, 0.f, 0.f);
#pragma unroll
        for (int i = 0; i < 8; i++) xzp[(long)i * 50176 + gt] = zero;
    }

    const float4* hp = (const float4*)(g_hidden + (long)n * DM);
    float4* rp = (float4*)(g_resid + (long)n * DM);
    float4 h0 = hp[lane], h1 = hp[32 + lane];
    if (!first) {
        float4 r0 = rp[lane], r1 = rp[32 + lane];
        h0.x += r0.x; h0.y += r0.y; h0.z += r0.z; h0.w += r0.w;
        h1.x += r1.x; h1.y += r1.y; h1.z += r1.z; h1.w += r1.w;
    }
    rp[lane] = h0; rp[32 + lane] = h1;
    float ss = h0.x*h0.x + h0.y*h0.y + h0.z*h0.z + h0.w*h0.w
             + h1.x*h1.x + h1.y*h1.y + h1.z*h1.z + h1.w*h1.w;
#pragma unroll
    for (int m = 16; m; m >>= 1) ss += __shfl_xor_sync(0xffffffffu, ss, m);
    if (lane == 0) g_scale[n] = rsqrtf(ss / (float)DM + 1e-5f);
}

// ---------------- conv + silu + transpose  (and z-gate transpose) -------------
// Also zeroes g_hidden (for out_proj atomics) and g_dbl (for xproj atomics).
#define CT 64
#define CD 32
__global__ void __launch_bounds__(256)
conv_kernel(const float* __restrict__ cwf, const float* __restrict__ cbf,
            const float* __restrict__ cwb, const float* __restrict__ cbb) {
    {
        int bid = (blockIdx.z * gridDim.y + blockIdx.y) * gridDim.x + blockIdx.x;
        int gid = bid * 256 + threadIdx.x;
        const int NH4 = NT * DM / 4;          // 100352
        const int ND4 = 2 * NT * 48 / 4;      // 37632
        if (gid < NH4) ((float4*)g_hidden)[gid] = make_float4(0.f, 0.f, 0.f, 0.f);
        else if (gid < NH4 + ND4) ((float4*)g_dbl)[gid - NH4] = make_float4(0.f, 0.f, 0.f, 0.f);
    }
    __shared__ float tile[CT + 3][CD + 1];
    int mode = blockIdx.z / BB;
    int b = blockIdx.z % BB;
    int t0 = blockIdx.x * CT;
    int d0 = blockIdx.y * CD;
    int tid = threadIdx.x;
    int colbase = (mode == 2 ? DI : 0) + d0;

    int rr = tid >> 3, cc = (tid & 7) * 4;
#pragma unroll
    for (int it = 0; it < 3; it++) {
        int r = it * 32 + rr;
        if (r < CT + 3) {
            int ss = t0 - 3 + r;
            float4 v = make_float4(0.f, 0.f, 0.f, 0.f);
            if (ss >= 0 && ss < LSEQ) {
                int src = (mode == 1) ? (LSEQ - 1 - ss) : ss;
                v = *(const float4*)&g_xz[(long)(b * LSEQ + src) * (2 * DI) + colbase + cc];
            }
            tile[r][cc + 0] = v.x; tile[r][cc + 1] = v.y;
            tile[r][cc + 2] = v.z; tile[r][cc + 3] = v.w;
        }
    }
    __syncthreads();

    int tl = tid & 63, dg = tid >> 6;
    int tt = t0 + tl;
    if (tt >= LSEQ) return;
    if (mode == 2) {
#pragma unroll
        for (int i = 0; i < 8; i++) {
            int dl = dg * 8 + i;
            float v = siluf(tile[tl + 3][dl]);
            g_gz[(long)(d0 + dl) * NT + b * LSEQ + tt] = v;
        }
    } else {
        const float* cw = mode ? cwb : cwf;
        const float* cb = mode ? cbb : cbf;
#pragma unroll
        for (int i = 0; i < 8; i++) {
            int dl = dg * 8 + i;
            int d = d0 + dl;
            float acc = cb[d];
#pragma unroll
            for (int k = 0; k < 4; k++)
                acc = fmaf(tile[tl + k][dl], cw[d * 4 + k], acc);
            g_xs[((long)mode * DI + d) * NT + b * LSEQ + tt] = siluf(acc);
        }
    }
}

// ---------------- chunked SSM scan (two-pass, transposed inputs) --------------
__global__ void scan_pass1_kernel(int layer) {
    int dir = blockIdx.z;
    int c = blockIdx.y;
    int tid = threadIdx.x;
    int grp = tid >> 4, s = tid & 15;
    int ch = blockIdx.x * 16 + grp;
    int b = ch >> 9, d = ch & (DI - 1);
    int e = ((dir * BB + b) * DI + d) * DSTATE + s;

    const float A_ds = g_A[(dir * NDEPTH + layer) * DI * DSTATE + d * DSTATE + s];
    long base = ((long)dir * DI + d) * NT + b * LSEQ;
    const float* dtp = g_dt + base;
    const float* xsp = g_xs + base;
    const float* dblp = g_dbl + ((long)dir * NT + b * LSEQ) * 48;

    float P = 1.f, q = 0.f;
    int t0 = c * CLEN;
    for (int tb = 0; tb < CLEN; tb += 16) {
        int tt = t0 + tb;
        float dtv = dtp[tt + s];
        float uv  = xsp[tt + s];
#pragma unroll
        for (int j = 0; j < 16; j++) {
            float dt = __shfl_sync(0xffffffffu, dtv, j, 16);
            float u  = __shfl_sync(0xffffffffu, uv,  j, 16);
            float Bv = dblp[(tt + j) * 48 + 16 + s];
            float a = __expf(dt * A_ds);
            P *= a;
            q = fmaf(a, q, (dt * u) * Bv);
        }
    }
    g_P[c][e] = P;
    g_q[c][e] = q;
}

__global__ void scan_pass2_kernel(int layer, const float* __restrict__ Dsf,
                                  const float* __restrict__ Dsb) {
    int dir = blockIdx.z;
    int c = blockIdx.y;
    int tid = threadIdx.x;
    int grp = tid >> 4, s = tid & 15;
    int ch = blockIdx.x * 16 + grp;
    int b = ch >> 9, d = ch & (DI - 1);
    int e = ((dir * BB + b) * DI + d) * DSTATE + s;

    const float A_ds = g_A[(dir * NDEPTH + layer) * DI * DSTATE + d * DSTATE + s];
    const float Dd = (dir ? Dsb : Dsf)[d];
    long base = ((long)dir * DI + d) * NT + b * LSEQ;
    const float* dtp = g_dt + base;
    const float* xsp = g_xs + base;
    const float* dblp = g_dbl + ((long)dir * NT + b * LSEQ) * 48;
    const float* gzp = g_gz + (long)d * NT + b * LSEQ;
    float* yp = g_y + base;

    float h = 0.f;
    for (int cc = 0; cc < c; cc++) h = fmaf(g_P[cc][e], h, g_q[cc][e]);

    int t0 = c * CLEN;
    float yb0 = 0.f, yb1 = 0.f, yb2 = 0.f;
    for (int tb = 0; tb < CLEN; tb += 16) {
        int tt = t0 + tb;
        float dtv = dtp[tt + s];
        float uv  = xsp[tt + s];
#pragma unroll
        for (int j = 0; j < 16; j++) {
            int ss = tt + j;
            float dt = __shfl_sync(0xffffffffu, dtv, j, 16);
            float u  = __shfl_sync(0xffffffffu, uv,  j, 16);
            float Bv = dblp[ss * 48 + 16 + s];
            float Cv = dblp[ss * 48 + 32 + s];
            float a = __expf(dt * A_ds);
            h = fmaf(a, h, (dt * u) * Bv);
            float p = h * Cv;
            p += __shfl_xor_sync(0xffffffffu, p, 8);
            p += __shfl_xor_sync(0xffffffffu, p, 4);
            p += __shfl_xor_sync(0xffffffffu, p, 2);
            p += __shfl_xor_sync(0xffffffffu, p, 1);
            if (s == 0) {
                int orig = dir ? (LSEQ - 1 - ss) : ss;
                float val = (p + Dd * u) * gzp[orig];
                if ((j & 3) == 0) yb0 = val;
                else if ((j & 3) == 1) yb1 = val;
                else if ((j & 3) == 2) yb2 = val;
                else {
                    float4 o = dir ? make_float4(val, yb2, yb1, yb0)
                                   : make_float4(yb0, yb1, yb2, val);
                    int addr = dir ? (LSEQ - 1 - ss) : (ss - 3);
                    *(float4*)&yp[addr] = o;
                }
            }
        }
    }
}

// ---------------- heads (with fused final rmsnorm) ----------------------------
__global__ void heads_kernel(const float* __restrict__ normf_w,
                             const float* __restrict__ bw1, const float* __restrict__ bb1,
                             const float* __restrict__ bw2, const float* __restrict__ bb2,
                             const float* __restrict__ pw1, const float* __restrict__ pb1,
                             const float* __restrict__ pw2, const float* __restrict__ pb2,
                             float* __restrict__ out) {
    int h = blockIdx.x;
    int b = blockIdx.y;
    int tid = threadIdx.x;
    __shared__ float sin_[DM];
    __shared__ float hidv[DM];
    __shared__ float sw[8];

    int n = b * LSEQ + h;
    float r = g_resid[n * DM + tid] + g_hidden[n * DM + tid];
    float ss = r * r;
#pragma unroll
    for (int m = 16; m; m >>= 1) ss += __shfl_xor_sync(0xffffffffu, ss, m);
    if ((tid & 31) == 0) sw[tid >> 5] = ss;
    __syncthreads();
    float tot = 0.f;
#pragma unroll
    for (int i = 0; i < 8; i++) tot += sw[i];
    float sc = rsqrtf(tot / (float)DM + 1e-5f);
    sin_[tid] = r * sc * normf_w[tid];
    __syncthreads();

    const float *w1, *b1, *w2, *b2;
    int nout; bool sig;
    if (h == 0) { w1 = bw1; b1 = bb1; w2 = bw2; b2 = bb2; nout = 3; sig = false; }
    else {
        int i = h - 1;
        w1 = pw1 + (long)i * DM * DM; b1 = pb1 + i * DM;
        w2 = pw2 + i * 2 * DM;        b2 = pb2 + i * 2;
        nout = 2; sig = true;
    }
    float acc = b1[tid];
    for (int k = 0; k < DM; k++) acc = fmaf(sin_[k], w1[(long)tid * DM + k], acc);
    hidv[tid] = fmaxf(acc, 0.f);
    __syncthreads();

    int w = tid >> 5, lane = tid & 31;
    if (w < nout) {
        float a = 0.f;
        for (int k = lane; k < DM; k += 32) a += hidv[k] * w2[w * DM + k];
#pragma unroll
        for (int m = 16; m; m >>= 1) a += __shfl_xor_sync(0xffffffffu, a, m);
        if (lane == 0) {
            float v = a + b2[w];
            if (sig) v = 1.f / (1.f + __expf(-v));
            int o = (h == 0) ? (b * 11 + w) : (b * 11 + 3 + (h - 1) * 2 + w);
            out[o] = v;
        }
    }
}

// ---------------- host side ----------------
extern "C" void kernel_launch(void* const* d_in, const int* in_sizes, int n_in,
                              void* d_out, int out_size) {
    (void)in_sizes; (void)n_in; (void)out_size;
    const float* x        = (const float*)d_in[0];
    const float* patch_w  = (const float*)d_in[1];
    const float* patch_b  = (const float*)d_in[2];
    const float* pos      = (const float*)d_in[3];
    const float* temp     = (const float*)d_in[4];
    const float* in_proj  = (const float*)d_in[5];
    const float* convf_w  = (const float*)d_in[6];
    const float* convf_b  = (const float*)d_in[7];
    const float* xprojf   = (const float*)d_in[8];
    const float* dtf_w    = (const float*)d_in[9];
    const float* dtf_b    = (const float*)d_in[10];
    const float* A_logf   = (const float*)d_in[11];
    const float* Dsf      = (const float*)d_in[12];
    const float* convb_w  = (const float*)d_in[13];
    const float* convb_b  = (const float*)d_in[14];
    const float* xprojb   = (const float*)d_in[15];
    const float* dtb_w    = (const float*)d_in[16];
    const float* dtb_b    = (const float*)d_in[17];
    const float* A_logb   = (const float*)d_in[18];
    const float* Dsb      = (const float*)d_in[19];
    const float* out_proj = (const float*)d_in[20];
    const float* norm_w   = (const float*)d_in[21];
    const float* normf_w  = (const float*)d_in[22];
    const float* bbox_w1  = (const float*)d_in[23];
    const float* bbox_b1  = (const float*)d_in[24];
    const float* bbox_w2  = (const float*)d_in[25];
    const float* bbox_b2  = (const float*)d_in[26];
    const float* pix_w1   = (const float*)d_in[27];
    const float* pix_b1   = (const float*)d_in[28];
    const float* pix_w2   = (const float*)d_in[29];
    const float* pix_b2   = (const float*)d_in[30];
    float* out = (float*)d_out;

    float *p_im2col, *p_hidden, *p_resid, *p_xz, *p_xs, *p_dbl, *p_dt, *p_y;
    cudaGetSymbolAddress((void**)&p_im2col, g_im2col);
    cudaGetSymbolAddress((void**)&p_hidden, g_hidden);
    cudaGetSymbolAddress((void**)&p_resid,  g_resid);
    cudaGetSymbolAddress((void**)&p_xz,     g_xz);
    cudaGetSymbolAddress((void**)&p_xs,     g_xs);
    cudaGetSymbolAddress((void**)&p_dbl,    g_dbl);
    cudaGetSymbolAddress((void**)&p_dt,     g_dt);
    cudaGetSymbolAddress((void**)&p_y,      g_y);

    const int GY = (NT + TBM - 1) / TBM;   // 25

    im2col_kernel<<<(NT * KPATCH + 255) / 256, 256>>>(x, A_logf, A_logb);

    // patch embed: N=256, K=768, split-K 4, atomic, EPI=2 -> 400 blocks
    mma_gemm_kernel<2, true, false, false, false><<<dim3(4, GY, 4), 128>>>(
        p_im2col, nullptr, KPATCH, patch_w, nullptr, p_hidden, DM,
        NT, DM, KPATCH, 4, patch_b, nullptr, pos, temp, 0, 0, nullptr);

    for (int i = 0; i < NDEPTH; i++) {
        addnorm_kernel<<<NT / 4, 128>>>(i == 0);
        // in_proj: ANORM, N=1024, K=256, split-K 2, atomic -> 800 blocks
        mma_gemm_kernel<0, true, false, false, true><<<dim3(16, GY, 2), 128>>>(
            p_resid, nullptr, DM, in_proj + (long)i * 2 * DI * DM, nullptr,
            p_xz, 2 * DI, NT, 2 * DI, DM, 2, nullptr, nullptr, nullptr, nullptr, 0, 0,
            norm_w + i * DM);
        // conv + silu + transpose (fwd, bwd, z-gate); zeroes hidden & dbl
        conv_kernel<<<dim3((LSEQ + CT - 1) / CT, DI / CD, 3 * BB), 256>>>(
            convf_w + (long)i * DI * 4, convf_b + i * DI,
            convb_w + (long)i * DI * 4, convb_b + i * DI);
        // xproj: TRANSA, N=48, K=512, dirs 2, split-K 8, atomic -> 400 blocks
        mma_gemm_kernel<0, true, true, false, false><<<dim3(1, GY, 16), 128>>>(
            p_xs, nullptr, NT, xprojf + (long)i * 48 * DI, xprojb + (long)i * 48 * DI,
            p_dbl, 48, NT, 48, DI, 8, nullptr, nullptr, nullptr, nullptr,
            (long)DI * NT, (long)NT * 48, nullptr);
        // dt: N=512, K=16, dirs 2, softplus, TRANSC -> dt_T (400 blocks)
        mma_gemm_kernel<1, false, false, true, false><<<dim3(8, GY, 2), 128>>>(
            p_dbl, nullptr, 48, dtf_w + (long)i * DI * DTR, dtb_w + (long)i * DI * DTR,
            p_dt, NT, NT, DI, DTR, 1, dtf_b + i * DI, dtb_b + i * DI, nullptr, nullptr,
            (long)NT * 48, (long)DI * NT, nullptr);
        scan_pass1_kernel<<<dim3(64, NCHUNK, 2), 256>>>(i);
        scan_pass2_kernel<<<dim3(64, NCHUNK, 2), 256>>>(i, Dsf + i * DI, Dsb + i * DI);
        // out_proj: TRANSA, N=256, K=512, split-K 4, atomic -> 400 blocks
        mma_gemm_kernel<0, true, true, false, false><<<dim3(4, GY, 4), 128>>>(
            p_y, p_y + (long)DI * NT, NT, out_proj + (long)i * DM * DI, nullptr,
            p_hidden, DM, NT, DM, DI, 4, nullptr, nullptr, nullptr, nullptr, 0, 0, nullptr);
    }

    heads_kernel<<<dim3(5, BB), 256>>>(normf_w, bbox_w1, bbox_b1, bbox_w2, bbox_b2,
                                       pix_w1, pix_b1, pix_w2, pix_b2, out);
}

// round 14
// speedup vs baseline: 2.4604x; 1.0103x over previous
#include <cuda_runtime.h>
#include <math.h>
#include <stdint.h>

#define BB      2
#define FRAMES  4
#define LSEQ    784
#define NT      1568
#define DM      256
#define DI      512
#define DSTATE  16
#define DTR     16
#define NDEPTH  12
#define NPATCH  196
#define KPATCH  768
#define NCHUNK  7
#define CLEN    112
#define NGRP    (2 * BB * DI * DSTATE)

// ---------------- scratch ----------------
__device__ float g_im2col[NT * KPATCH];
__device__ float g_hidden[NT * DM];
__device__ float g_resid [NT * DM];
__device__ float g_scale [NT];
__device__ float g_xz    [NT * 2 * DI];
__device__ float g_xs    [2 * DI * NT];   // TRANSPOSED: [dir][d][b*784+t]
__device__ float g_gz    [DI * NT];       // TRANSPOSED silu(z)
__device__ float g_dbl   [2 * NT * 48];
__device__ float g_dt    [2 * DI * NT];   // TRANSPOSED
__device__ float g_y     [2 * DI * NT];   // TRANSPOSED
__device__ float g_A     [2 * NDEPTH * DI * DSTATE];
__device__ float g_P     [NCHUNK][NGRP];
__device__ float g_q     [NCHUNK][NGRP];

static __device__ __forceinline__ float siluf(float x) {
    return x / (1.f + __expf(-x));
}
static __device__ __forceinline__ float softplusf(float x) {
    return (x > 20.f) ? x : log1pf(__expf(x));
}
static __device__ __forceinline__ uint32_t f2tf32(float x) {
    uint32_t r;
    asm("cvt.rna.tf32.f32 %0, %1;" : "=r"(r) : "f"(x));
    return r;
}
static __device__ __forceinline__ void mma_tf32(float* d, const uint32_t* a, const uint32_t* b) {
    asm volatile(
        "mma.sync.aligned.m16n8k8.row.col.f32.tf32.tf32.f32 "
        "{%0,%1,%2,%3}, {%4,%5,%6,%7}, {%8,%9}, {%0,%1,%2,%3};"
        : "+f"(d[0]), "+f"(d[1]), "+f"(d[2]), "+f"(d[3])
        : "r"(a[0]), "r"(a[1]), "r"(a[2]), "r"(a[3]), "r"(b[0]), "r"(b[1]));
}

// im2col + zero g_hidden + prep A (folded)
__global__ void im2col_kernel(const float* __restrict__ x,
                              const float* __restrict__ Af,
                              const float* __restrict__ Ab) {
    int e = blockIdx.x * blockDim.x + threadIdx.x;
    if (e >= NT * KPATCH) return;
    if (e < NT * DM) g_hidden[e] = 0.f;
    const int NA = NDEPTH * DI * DSTATE;
    if (e < NA) {
        g_A[e]      = -expf(Af[e]);
        g_A[NA + e] = -expf(Ab[e]);
    }
    int n = e / KPATCH, k = e % KPATCH;
    int b = n / LSEQ, tl = n % LSEQ;
    int t = tl / NPATCH, p = tl % NPATCH;
    int ph = p / 14, pw = p % 14;
    int ci = k / 256, rem = k % 256;
    int ii = rem / 16, jj = rem % 16;
    long off = (((long)(b * 3 + ci) * FRAMES + t) * 224 + (ph * 16 + ii)) * 224 + (pw * 16 + jj);
    g_im2col[e] = x[off];
}

// ---------------- TF32 tensor-core GEMM, 64x64 tile, 4 warps ------------------
// C[M,N] = (A [+A2]) @ W^T ; W is N x K row-major. z = dir*SK + ks.
// TRANSA: A col-major A[k*lda + row]. TRANSC: C written transposed, smem-staged.
// ANORM: A element scaled by g_scale[row]*nw[k] (fused rmsnorm for in_proj).
// EPI: 0 none, 1 softplus(+bias), 2 patch epilogue (ks==0 only).
#define TBM  64
#define TBN  64
#define TBK  16
#define TBKP 20
template <int EPI, bool ATOMIC, bool TRANSA, bool TRANSC, bool ANORM>
__global__ void __launch_bounds__(128, 8)
mma_gemm_kernel(const float* __restrict__ A, const float* __restrict__ A2, int lda,
                const float* __restrict__ W, const float* __restrict__ Wb,
                float* __restrict__ C, int ldc,
                int M, int N, int K, int SK,
                const float* __restrict__ bias, const float* __restrict__ biasb,
                const float* __restrict__ pos, const float* __restrict__ temp,
                long strideA, long strideC,
                const float* __restrict__ nw) {
    __shared__ uint32_t As[2][TBM][TBKP];
    __shared__ uint32_t Bs[2][TBN][TBKP];

    int z = blockIdx.z;
    int dir = z / SK, ks = z - dir * SK;
    if (dir) { A += strideA; C += strideC; W = Wb; bias = biasb; if (A2) A2 += strideA; }
    int Kc = K / SK;
    int kbase = ks * Kc;
    int nk = Kc / TBK;

    int tid = threadIdx.x;
    int lane = tid & 31;
    int wid = tid >> 5;
    int wm = wid >> 1, wn = wid & 1;
    int qr = lane >> 2, qc = lane & 3;

    int rowBase = blockIdx.y * TBM;
    int colBase = blockIdx.x * TBN;

    float rowsc = 1.f;
    if (ANORM) {
        int r = rowBase + (tid >> 1);
        rowsc = (r < M) ? g_scale[r] : 0.f;
    }

    auto load_tile = [&](int k0, int buf) {
        if (TRANSA) {
#pragma unroll
            for (int it = 0; it < 2; it++) {
                int item = it * 128 + tid;
                int kk = item >> 4;
                int r4 = (item & 15) * 4;
                float4 v = make_float4(0.f, 0.f, 0.f, 0.f);
                int row = rowBase + r4;
                if (row < M) {
                    v = *(const float4*)&A[(long)(k0 + kk) * lda + row];
                    if (A2) {
                        float4 w = *(const float4*)&A2[(long)(k0 + kk) * lda + row];
                        v.x += w.x; v.y += w.y; v.z += w.z; v.w += w.w;
                    }
                }
                As[buf][r4 + 0][kk] = f2tf32(v.x);
                As[buf][r4 + 1][kk] = f2tf32(v.y);
                As[buf][r4 + 2][kk] = f2tf32(v.z);
                As[buf][r4 + 3][kk] = f2tf32(v.w);
            }
        } else {
            int lr = tid >> 1;
            int lc = (tid & 1) * 8;
            int r = rowBase + lr;
            float4 a0 = make_float4(0.f, 0.f, 0.f, 0.f);
            float4 a1 = make_float4(0.f, 0.f, 0.f, 0.f);
            if (r < M) {
                a0 = *(const float4*)&A[(long)r * lda + k0 + lc];
                a1 = *(const float4*)&A[(long)r * lda + k0 + lc + 4];
                if (A2) {
                    float4 w0 = *(const float4*)&A2[(long)r * lda + k0 + lc];
                    float4 w1 = *(const float4*)&A2[(long)r * lda + k0 + lc + 4];
                    a0.x += w0.x; a0.y += w0.y; a0.z += w0.z; a0.w += w0.w;
                    a1.x += w1.x; a1.y += w1.y; a1.z += w1.z; a1.w += w1.w;
                }
            }
            if (ANORM) {
                float4 n0 = *(const float4*)&nw[k0 + lc];
                float4 n1 = *(const float4*)&nw[k0 + lc + 4];
                a0.x *= rowsc * n0.x; a0.y *= rowsc * n0.y;
                a0.z *= rowsc * n0.z; a0.w *= rowsc * n0.w;
                a1.x *= rowsc * n1.x; a1.y *= rowsc * n1.y;
                a1.z *= rowsc * n1.z; a1.w *= rowsc * n1.w;
            }
            As[buf][lr][lc + 0] = f2tf32(a0.x); As[buf][lr][lc + 1] = f2tf32(a0.y);
            As[buf][lr][lc + 2] = f2tf32(a0.z); As[buf][lr][lc + 3] = f2tf32(a0.w);
            As[buf][lr][lc + 4] = f2tf32(a1.x); As[buf][lr][lc + 5] = f2tf32(a1.y);
            As[buf][lr][lc + 6] = f2tf32(a1.z); As[buf][lr][lc + 7] = f2tf32(a1.w);
        }
        {
            int lr = tid >> 1;
            int lc = (tid & 1) * 8;
            int col = colBase + lr;
            float4 b0 = make_float4(0.f, 0.f, 0.f, 0.f);
            float4 b1 = make_float4(0.f, 0.f, 0.f, 0.f);
            if (col < N) {
                b0 = *(const float4*)&W[(long)col * K + k0 + lc];
                b1 = *(const float4*)&W[(long)col * K + k0 + lc + 4];
            }
            Bs[buf][lr][lc + 0] = f2tf32(b0.x); Bs[buf][lr][lc + 1] = f2tf32(b0.y);
            Bs[buf][lr][lc + 2] = f2tf32(b0.z); Bs[buf][lr][lc + 3] = f2tf32(b0.w);
            Bs[buf][lr][lc + 4] = f2tf32(b1.x); Bs[buf][lr][lc + 5] = f2tf32(b1.y);
            Bs[buf][lr][lc + 6] = f2tf32(b1.z); Bs[buf][lr][lc + 7] = f2tf32(b1.w);
        }
    };

    float acc[2][4][4];
#pragma unroll
    for (int mi = 0; mi < 2; mi++)
#pragma unroll
        for (int ni = 0; ni < 4; ni++)
#pragma unroll
            for (int u = 0; u < 4; u++) acc[mi][ni][u] = 0.f;

    load_tile(kbase, 0);
    __syncthreads();

    for (int c = 0; c < nk; c++) {
        int cur = c & 1, nxt = cur ^ 1;
        if (c + 1 < nk) load_tile(kbase + (c + 1) * TBK, nxt);
#pragma unroll
        for (int c2 = 0; c2 < 2; c2++) {
            uint32_t af[2][4], bf[4][2];
#pragma unroll
            for (int mi = 0; mi < 2; mi++) {
                int r = wm * 32 + mi * 16 + qr;
                af[mi][0] = As[cur][r][c2 * 8 + qc];
                af[mi][1] = As[cur][r + 8][c2 * 8 + qc];
                af[mi][2] = As[cur][r][c2 * 8 + 4 + qc];
                af[mi][3] = As[cur][r + 8][c2 * 8 + 4 + qc];
            }
#pragma unroll
            for (int ni = 0; ni < 4; ni++) {
                int n = wn * 32 + ni * 8 + qr;
                bf[ni][0] = Bs[cur][n][c2 * 8 + qc];
                bf[ni][1] = Bs[cur][n][c2 * 8 + 4 + qc];
            }
#pragma unroll
            for (int mi = 0; mi < 2; mi++)
#pragma unroll
                for (int ni = 0; ni < 4; ni++)
                    mma_tf32(acc[mi][ni], af[mi], bf[ni]);
        }
        __syncthreads();
    }

    if (TRANSC) {
        __shared__ float stage[TBN][68];
#pragma unroll
        for (int mi = 0; mi < 2; mi++) {
#pragma unroll
            for (int ni = 0; ni < 4; ni++) {
                int r0 = wm * 32 + mi * 16 + qr;
                int c0 = wn * 32 + ni * 8 + 2 * qc;
#pragma unroll
                for (int u = 0; u < 4; u++) {
                    int rl = r0 + (u >= 2 ? 8 : 0);
                    int cl = c0 + (u & 1);
                    float v = acc[mi][ni][u];
                    if (EPI == 1) v = softplusf(v + bias[colBase + cl]);
                    stage[cl][rl] = v;
                }
            }
        }
        __syncthreads();
#pragma unroll
        for (int it = 0; it < 8; it++) {
            int item = it * 128 + tid;
            int col = item >> 4;
            int r = (item & 15) * 4;
            int row = rowBase + r;
            if (row < M) {
                float4 v = *(const float4*)&stage[col][r];
                *(float4*)&C[(long)(colBase + col) * ldc + row] = v;
            }
        }
    } else {
#pragma unroll
        for (int mi = 0; mi < 2; mi++) {
#pragma unroll
            for (int ni = 0; ni < 4; ni++) {
                int r0 = rowBase + wm * 32 + mi * 16 + qr;
                int c0 = colBase + wn * 32 + ni * 8 + 2 * qc;
#pragma unroll
                for (int u = 0; u < 4; u++) {
                    int row = r0 + (u >= 2 ? 8 : 0);
                    int col = c0 + (u & 1);
                    if (row >= M || col >= N) continue;
                    float v = acc[mi][ni][u];
                    if (EPI == 1) {
                        v = softplusf(v + bias[col]);
                    } else if (EPI == 2) {
                        if (ks == 0) {
                            int tl = row % LSEQ;
                            int t = tl / NPATCH, p = tl % NPATCH;
                            v += bias[col] + pos[p * DM + col] + temp[t * DM + col];
                        }
                    }
                    if (ATOMIC) atomicAdd(&C[(long)row * ldc + col], v);
                    else        C[(long)row * ldc + col] = v;
                }
            }
        }
    }
}

// ---------------- slim residual add + rms scale + zero g_xz -------------------
__global__ void __launch_bounds__(128)
addnorm_kernel(int first) {
    int wid = threadIdx.x >> 5, lane = threadIdx.x & 31;
    int n = blockIdx.x * 4 + wid;
    {
        int gt = blockIdx.x * 128 + threadIdx.x;
        float4* xzp = (float4*)g_xz;
        float4 zero = make_float4(0.f, 0.f, 0.f, 0.f);
#pragma unroll
        for (int i = 0; i < 8; i++) xzp[(long)i * 50176 + gt] = zero;
    }

    const float4* hp = (const float4*)(g_hidden + (long)n * DM);
    float4* rp = (float4*)(g_resid + (long)n * DM);
    float4 h0 = hp[lane], h1 = hp[32 + lane];
    if (!first) {
        float4 r0 = rp[lane], r1 = rp[32 + lane];
        h0.x += r0.x; h0.y += r0.y; h0.z += r0.z; h0.w += r0.w;
        h1.x += r1.x; h1.y += r1.y; h1.z += r1.z; h1.w += r1.w;
    }
    rp[lane] = h0; rp[32 + lane] = h1;
    float ss = h0.x*h0.x + h0.y*h0.y + h0.z*h0.z + h0.w*h0.w
             + h1.x*h1.x + h1.y*h1.y + h1.z*h1.z + h1.w*h1.w;
#pragma unroll
    for (int m = 16; m; m >>= 1) ss += __shfl_xor_sync(0xffffffffu, ss, m);
    if (lane == 0) g_scale[n] = rsqrtf(ss / (float)DM + 1e-5f);
}

// ---------------- conv + silu + transpose  (and z-gate transpose) -------------
#define CT 64
#define CD 32
__global__ void __launch_bounds__(256)
conv_kernel(const float* __restrict__ cwf, const float* __restrict__ cbf,
            const float* __restrict__ cwb, const float* __restrict__ cbb) {
    {
        int bid = (blockIdx.z * gridDim.y + blockIdx.y) * gridDim.x + blockIdx.x;
        int gid = bid * 256 + threadIdx.x;
        const int NH4 = NT * DM / 4;          // 100352
        const int ND4 = 2 * NT * 48 / 4;      // 37632
        if (gid < NH4) ((float4*)g_hidden)[gid] = make_float4(0.f, 0.f, 0.f, 0.f);
        else if (gid < NH4 + ND4) ((float4*)g_dbl)[gid - NH4] = make_float4(0.f, 0.f, 0.f, 0.f);
    }
    __shared__ float tile[CT + 3][CD + 1];
    int mode = blockIdx.z / BB;
    int b = blockIdx.z % BB;
    int t0 = blockIdx.x * CT;
    int d0 = blockIdx.y * CD;
    int tid = threadIdx.x;
    int colbase = (mode == 2 ? DI : 0) + d0;

    int rr = tid >> 3, cc = (tid & 7) * 4;
#pragma unroll
    for (int it = 0; it < 3; it++) {
        int r = it * 32 + rr;
        if (r < CT + 3) {
            int ss = t0 - 3 + r;
            float4 v = make_float4(0.f, 0.f, 0.f, 0.f);
            if (ss >= 0 && ss < LSEQ) {
                int src = (mode == 1) ? (LSEQ - 1 - ss) : ss;
                v = *(const float4*)&g_xz[(long)(b * LSEQ + src) * (2 * DI) + colbase + cc];
            }
            tile[r][cc + 0] = v.x; tile[r][cc + 1] = v.y;
            tile[r][cc + 2] = v.z; tile[r][cc + 3] = v.w;
        }
    }
    __syncthreads();

    int tl = tid & 63, dg = tid >> 6;
    int tt = t0 + tl;
    if (tt >= LSEQ) return;
    if (mode == 2) {
#pragma unroll
        for (int i = 0; i < 8; i++) {
            int dl = dg * 8 + i;
            float v = siluf(tile[tl + 3][dl]);
            g_gz[(long)(d0 + dl) * NT + b * LSEQ + tt] = v;
        }
    } else {
        const float* cw = mode ? cwb : cwf;
        const float* cb = mode ? cbb : cbf;
#pragma unroll
        for (int i = 0; i < 8; i++) {
            int dl = dg * 8 + i;
            int d = d0 + dl;
            float acc = cb[d];
#pragma unroll
            for (int k = 0; k < 4; k++)
                acc = fmaf(tile[tl + k][dl], cw[d * 4 + k], acc);
            g_xs[((long)mode * DI + d) * NT + b * LSEQ + tt] = siluf(acc);
        }
    }
}

// ---------------- chunked SSM scan (two-pass, transposed inputs) --------------
__global__ void scan_pass1_kernel(int layer) {
    int dir = blockIdx.z;
    int c = blockIdx.y;
    int tid = threadIdx.x;
    int grp = tid >> 4, s = tid & 15;
    int ch = blockIdx.x * 16 + grp;
    int b = ch >> 9, d = ch & (DI - 1);
    int e = ((dir * BB + b) * DI + d) * DSTATE + s;

    const float A_ds = g_A[(dir * NDEPTH + layer) * DI * DSTATE + d * DSTATE + s];
    long base = ((long)dir * DI + d) * NT + b * LSEQ;
    const float* dtp = g_dt + base;
    const float* xsp = g_xs + base;
    const float* dblp = g_dbl + ((long)dir * NT + b * LSEQ) * 48;

    float P = 1.f, q = 0.f;
    int t0 = c * CLEN;
    for (int tb = 0; tb < CLEN; tb += 16) {
        int tt = t0 + tb;
        float dtv = dtp[tt + s];
        float uv  = xsp[tt + s];
#pragma unroll
        for (int j = 0; j < 16; j++) {
            float dt = __shfl_sync(0xffffffffu, dtv, j, 16);
            float u  = __shfl_sync(0xffffffffu, uv,  j, 16);
            float Bv = dblp[(tt + j) * 48 + 16 + s];
            float a = __expf(dt * A_ds);
            P *= a;
            q = fmaf(a, q, (dt * u) * Bv);
        }
    }
    g_P[c][e] = P;
    g_q[c][e] = q;
}

__global__ void scan_pass2_kernel(int layer, const float* __restrict__ Dsf,
                                  const float* __restrict__ Dsb) {
    int dir = blockIdx.z;
    int c = blockIdx.y;
    int tid = threadIdx.x;
    int grp = tid >> 4, s = tid & 15;
    int ch = blockIdx.x * 16 + grp;
    int b = ch >> 9, d = ch & (DI - 1);
    int e = ((dir * BB + b) * DI + d) * DSTATE + s;

    const float A_ds = g_A[(dir * NDEPTH + layer) * DI * DSTATE + d * DSTATE + s];
    const float Dd = (dir ? Dsb : Dsf)[d];
    long base = ((long)dir * DI + d) * NT + b * LSEQ;
    const float* dtp = g_dt + base;
    const float* xsp = g_xs + base;
    const float* dblp = g_dbl + ((long)dir * NT + b * LSEQ) * 48;
    const float* gzp = g_gz + (long)d * NT + b * LSEQ;
    float* yp = g_y + base;

    float h = 0.f;
    for (int cc = 0; cc < c; cc++) h = fmaf(g_P[cc][e], h, g_q[cc][e]);

    int t0 = c * CLEN;
    float yb0 = 0.f, yb1 = 0.f, yb2 = 0.f;
    for (int tb = 0; tb < CLEN; tb += 16) {
        int tt = t0 + tb;
        float dtv = dtp[tt + s];
        float uv  = xsp[tt + s];
#pragma unroll
        for (int j = 0; j < 16; j++) {
            int ss = tt + j;
            float dt = __shfl_sync(0xffffffffu, dtv, j, 16);
            float u  = __shfl_sync(0xffffffffu, uv,  j, 16);
            float Bv = dblp[ss * 48 + 16 + s];
            float Cv = dblp[ss * 48 + 32 + s];
            float a = __expf(dt * A_ds);
            h = fmaf(a, h, (dt * u) * Bv);
            float p = h * Cv;
            p += __shfl_xor_sync(0xffffffffu, p, 8);
            p += __shfl_xor_sync(0xffffffffu, p, 4);
            p += __shfl_xor_sync(0xffffffffu, p, 2);
            p += __shfl_xor_sync(0xffffffffu, p, 1);
            if (s == 0) {
                int orig = dir ? (LSEQ - 1 - ss) : ss;
                float val = (p + Dd * u) * gzp[orig];
                if ((j & 3) == 0) yb0 = val;
                else if ((j & 3) == 1) yb1 = val;
                else if ((j & 3) == 2) yb2 = val;
                else {
                    float4 o = dir ? make_float4(val, yb2, yb1, yb0)
                                   : make_float4(yb0, yb1, yb2, val);
                    int addr = dir ? (LSEQ - 1 - ss) : (ss - 3);
                    *(float4*)&yp[addr] = o;
                }
            }
        }
    }
}

// ---------------- heads (with fused final rmsnorm) ----------------------------
__global__ void heads_kernel(const float* __restrict__ normf_w,
                             const float* __restrict__ bw1, const float* __restrict__ bb1,
                             const float* __restrict__ bw2, const float* __restrict__ bb2,
                             const float* __restrict__ pw1, const float* __restrict__ pb1,
                             const float* __restrict__ pw2, const float* __restrict__ pb2,
                             float* __restrict__ out) {
    int h = blockIdx.x;
    int b = blockIdx.y;
    int tid = threadIdx.x;
    __shared__ float sin_[DM];
    __shared__ float hidv[DM];
    __shared__ float sw[8];

    int n = b * LSEQ + h;
    float r = g_resid[n * DM + tid] + g_hidden[n * DM + tid];
    float ss = r * r;
#pragma unroll
    for (int m = 16; m; m >>= 1) ss += __shfl_xor_sync(0xffffffffu, ss, m);
    if ((tid & 31) == 0) sw[tid >> 5] = ss;
    __syncthreads();
    float tot = 0.f;
#pragma unroll
    for (int i = 0; i < 8; i++) tot += sw[i];
    float sc = rsqrtf(tot / (float)DM + 1e-5f);
    sin_[tid] = r * sc * normf_w[tid];
    __syncthreads();

    const float *w1, *b1, *w2, *b2;
    int nout; bool sig;
    if (h == 0) { w1 = bw1; b1 = bb1; w2 = bw2; b2 = bb2; nout = 3; sig = false; }
    else {
        int i = h - 1;
        w1 = pw1 + (long)i * DM * DM; b1 = pb1 + i * DM;
        w2 = pw2 + i * 2 * DM;        b2 = pb2 + i * 2;
        nout = 2; sig = true;
    }
    float acc = b1[tid];
    for (int k = 0; k < DM; k++) acc = fmaf(sin_[k], w1[(long)tid * DM + k], acc);
    hidv[tid] = fmaxf(acc, 0.f);
    __syncthreads();

    int w = tid >> 5, lane = tid & 31;
    if (w < nout) {
        float a = 0.f;
        for (int k = lane; k < DM; k += 32) a += hidv[k] * w2[w * DM + k];
#pragma unroll
        for (int m = 16; m; m >>= 1) a += __shfl_xor_sync(0xffffffffu, a, m);
        if (lane == 0) {
            float v = a + b2[w];
            if (sig) v = 1.f / (1.f + __expf(-v));
            int o = (h == 0) ? (b * 11 + w) : (b * 11 + 3 + (h - 1) * 2 + w);
            out[o] = v;
        }
    }
}

// ---------------- host side ----------------
extern "C" void kernel_launch(void* const* d_in, const int* in_sizes, int n_in,
                              void* d_out, int out_size) {
    (void)in_sizes; (void)n_in; (void)out_size;
    const float* x        = (const float*)d_in[0];
    const float* patch_w  = (const float*)d_in[1];
    const float* patch_b  = (const float*)d_in[2];
    const float* pos      = (const float*)d_in[3];
    const float* temp     = (const float*)d_in[4];
    const float* in_proj  = (const float*)d_in[5];
    const float* convf_w  = (const float*)d_in[6];
    const float* convf_b  = (const float*)d_in[7];
    const float* xprojf   = (const float*)d_in[8];
    const float* dtf_w    = (const float*)d_in[9];
    const float* dtf_b    = (const float*)d_in[10];
    const float* A_logf   = (const float*)d_in[11];
    const float* Dsf      = (const float*)d_in[12];
    const float* convb_w  = (const float*)d_in[13];
    const float* convb_b  = (const float*)d_in[14];
    const float* xprojb   = (const float*)d_in[15];
    const float* dtb_w    = (const float*)d_in[16];
    const float* dtb_b    = (const float*)d_in[17];
    const float* A_logb   = (const float*)d_in[18];
    const float* Dsb      = (const float*)d_in[19];
    const float* out_proj = (const float*)d_in[20];
    const float* norm_w   = (const float*)d_in[21];
    const float* normf_w  = (const float*)d_in[22];
    const float* bbox_w1  = (const float*)d_in[23];
    const float* bbox_b1  = (const float*)d_in[24];
    const float* bbox_w2  = (const float*)d_in[25];
    const float* bbox_b2  = (const float*)d_in[26];
    const float* pix_w1   = (const float*)d_in[27];
    const float* pix_b1   = (const float*)d_in[28];
    const float* pix_w2   = (const float*)d_in[29];
    const float* pix_b2   = (const float*)d_in[30];
    float* out = (float*)d_out;

    float *p_im2col, *p_hidden, *p_resid, *p_xz, *p_xs, *p_dbl, *p_dt, *p_y;
    cudaGetSymbolAddress((void**)&p_im2col, g_im2col);
    cudaGetSymbolAddress((void**)&p_hidden, g_hidden);
    cudaGetSymbolAddress((void**)&p_resid,  g_resid);
    cudaGetSymbolAddress((void**)&p_xz,     g_xz);
    cudaGetSymbolAddress((void**)&p_xs,     g_xs);
    cudaGetSymbolAddress((void**)&p_dbl,    g_dbl);
    cudaGetSymbolAddress((void**)&p_dt,     g_dt);
    cudaGetSymbolAddress((void**)&p_y,      g_y);

    const int GY = (NT + TBM - 1) / TBM;   // 25

    im2col_kernel<<<(NT * KPATCH + 255) / 256, 256>>>(x, A_logf, A_logb);

    // patch embed: N=256, K=768, split-K 8, atomic, EPI=2 -> 800 blocks
    mma_gemm_kernel<2, true, false, false, false><<<dim3(4, GY, 8), 128>>>(
        p_im2col, nullptr, KPATCH, patch_w, nullptr, p_hidden, DM,
        NT, DM, KPATCH, 8, patch_b, nullptr, pos, temp, 0, 0, nullptr);

    for (int i = 0; i < NDEPTH; i++) {
        addnorm_kernel<<<NT / 4, 128>>>(i == 0);
        // in_proj: ANORM, N=1024, K=256, split-K 4, atomic -> 1600 blocks
        mma_gemm_kernel<0, true, false, false, true><<<dim3(16, GY, 4), 128>>>(
            p_resid, nullptr, DM, in_proj + (long)i * 2 * DI * DM, nullptr,
            p_xz, 2 * DI, NT, 2 * DI, DM, 4, nullptr, nullptr, nullptr, nullptr, 0, 0,
            norm_w + i * DM);
        // conv + silu + transpose (fwd, bwd, z-gate); zeroes hidden & dbl
        conv_kernel<<<dim3((LSEQ + CT - 1) / CT, DI / CD, 3 * BB), 256>>>(
            convf_w + (long)i * DI * 4, convf_b + i * DI,
            convb_w + (long)i * DI * 4, convb_b + i * DI);
        // xproj: TRANSA, N=48, K=512, dirs 2, split-K 16, atomic -> 800 blocks
        mma_gemm_kernel<0, true, true, false, false><<<dim3(1, GY, 32), 128>>>(
            p_xs, nullptr, NT, xprojf + (long)i * 48 * DI, xprojb + (long)i * 48 * DI,
            p_dbl, 48, NT, 48, DI, 16, nullptr, nullptr, nullptr, nullptr,
            (long)DI * NT, (long)NT * 48, nullptr);
        // dt: N=512, K=16, dirs 2, softplus, TRANSC -> dt_T (400 blocks)
        mma_gemm_kernel<1, false, false, true, false><<<dim3(8, GY, 2), 128>>>(
            p_dbl, nullptr, 48, dtf_w + (long)i * DI * DTR, dtb_w + (long)i * DI * DTR,
            p_dt, NT, NT, DI, DTR, 1, dtf_b + i * DI, dtb_b + i * DI, nullptr, nullptr,
            (long)NT * 48, (long)DI * NT, nullptr);
        scan_pass1_kernel<<<dim3(64, NCHUNK, 2), 256>>>(i);
        scan_pass2_kernel<<<dim3(64, NCHUNK, 2), 256>>>(i, Dsf + i * DI, Dsb + i * DI);
        // out_proj: TRANSA, N=256, K=512, split-K 8, atomic -> 800 blocks
        mma_gemm_kernel<0, true, true, false, false><<<dim3(4, GY, 8), 128>>>(
            p_y, p_y + (long)DI * NT, NT, out_proj + (long)i * DM * DI, nullptr,
            p_hidden, DM, NT, DM, DI, 8, nullptr, nullptr, nullptr, nullptr, 0, 0, nullptr);
    }

    heads_kernel<<<dim3(5, BB), 256>>>(normf_w, bbox_w1, bbox_b1, bbox_w2, bbox_b2,
                                       pix_w1, pix_b1, pix_w2, pix_b2, out);
}

// round 16
// speedup vs baseline: 2.5144x; 1.0219x over previous
#include <cuda_runtime.h>
#include <math.h>
#include <stdint.h>

#define BB      2
#define FRAMES  4
#define LSEQ    784
#define NT      1568
#define DM      256
#define DI      512
#define DSTATE  16
#define DTR     16
#define NDEPTH  12
#define NPATCH  196
#define KPATCH  768
#define NCHUNK  7
#define CLEN    112
#define NGRP    (2 * BB * DI * DSTATE)

// ---------------- scratch ----------------
__device__ float g_im2col[NT * KPATCH];
__device__ float g_hidden[NT * DM];
__device__ float g_resid [NT * DM];
__device__ float g_scale [NT];
__device__ float g_xz    [NT * 2 * DI];
__device__ float g_xs    [2 * DI * NT];   // TRANSPOSED: [dir][d][b*784+t]
__device__ float g_gz    [DI * NT];       // TRANSPOSED silu(z)
__device__ float g_dbl   [2 * NT * 48];
__device__ float g_dt    [2 * DI * NT];   // TRANSPOSED
__device__ float g_y     [2 * DI * NT];   // TRANSPOSED
__device__ float g_A     [2 * NDEPTH * DI * DSTATE];
__device__ float g_P     [NCHUNK][NGRP];
__device__ float g_q     [NCHUNK][NGRP];

static __device__ __forceinline__ float siluf(float x) {
    return x / (1.f + __expf(-x));
}
static __device__ __forceinline__ float softplusf(float x) {
    return (x > 20.f) ? x : log1pf(__expf(x));
}
static __device__ __forceinline__ uint32_t f2tf32(float x) {
    uint32_t r;
    asm("cvt.rna.tf32.f32 %0, %1;" : "=r"(r) : "f"(x));
    return r;
}
static __device__ __forceinline__ void mma_tf32(float* d, const uint32_t* a, const uint32_t* b) {
    asm volatile(
        "mma.sync.aligned.m16n8k8.row.col.f32.tf32.tf32.f32 "
        "{%0,%1,%2,%3}, {%4,%5,%6,%7}, {%8,%9}, {%0,%1,%2,%3};"
        : "+f"(d[0]), "+f"(d[1]), "+f"(d[2]), "+f"(d[3])
        : "r"(a[0]), "r"(a[1]), "r"(a[2]), "r"(a[3]), "r"(b[0]), "r"(b[1]));
}

// im2col + zero g_hidden + prep A (folded)
__global__ void im2col_kernel(const float* __restrict__ x,
                              const float* __restrict__ Af,
                              const float* __restrict__ Ab) {
    int e = blockIdx.x * blockDim.x + threadIdx.x;
    if (e >= NT * KPATCH) return;
    if (e < NT * DM) g_hidden[e] = 0.f;
    const int NA = NDEPTH * DI * DSTATE;
    if (e < NA) {
        g_A[e]      = -expf(Af[e]);
        g_A[NA + e] = -expf(Ab[e]);
    }
    int n = e / KPATCH, k = e % KPATCH;
    int b = n / LSEQ, tl = n % LSEQ;
    int t = tl / NPATCH, p = tl % NPATCH;
    int ph = p / 14, pw = p % 14;
    int ci = k / 256, rem = k % 256;
    int ii = rem / 16, jj = rem % 16;
    long off = (((long)(b * 3 + ci) * FRAMES + t) * 224 + (ph * 16 + ii)) * 224 + (pw * 16 + jj);
    g_im2col[e] = x[off];
}

// ---------------- TF32 tensor-core GEMM, 64x64 tile, 4 warps ------------------
// C[M,N] = (A [+A2]) @ W^T ; W is N x K row-major. z = dir*SK + ks.
// TRANSA: A col-major A[k*lda + row]. TRANSC: C written transposed, smem-staged.
// ANORM: A element scaled by g_scale[row]*nw[k] (fused rmsnorm for in_proj).
// EPI: 0 none, 1 softplus(+bias), 2 patch epilogue (ks==0 only).
#define TBM  64
#define TBN  64
#define TBK  16
#define TBKP 20
template <int EPI, bool ATOMIC, bool TRANSA, bool TRANSC, bool ANORM>
__global__ void __launch_bounds__(128, 8)
mma_gemm_kernel(const float* __restrict__ A, const float* __restrict__ A2, int lda,
                const float* __restrict__ W, const float* __restrict__ Wb,
                float* __restrict__ C, int ldc,
                int M, int N, int K, int SK,
                const float* __restrict__ bias, const float* __restrict__ biasb,
                const float* __restrict__ pos, const float* __restrict__ temp,
                long strideA, long strideC,
                const float* __restrict__ nw) {
    __shared__ uint32_t As[2][TBM][TBKP];
    __shared__ uint32_t Bs[2][TBN][TBKP];

    int z = blockIdx.z;
    int dir = z / SK, ks = z - dir * SK;
    if (dir) { A += strideA; C += strideC; W = Wb; bias = biasb; if (A2) A2 += strideA; }
    int Kc = K / SK;
    int kbase = ks * Kc;
    int nk = Kc / TBK;

    int tid = threadIdx.x;
    int lane = tid & 31;
    int wid = tid >> 5;
    int wm = wid >> 1, wn = wid & 1;
    int qr = lane >> 2, qc = lane & 3;

    int rowBase = blockIdx.y * TBM;
    int colBase = blockIdx.x * TBN;

    float rowsc = 1.f;
    if (ANORM) {
        int r = rowBase + (tid >> 1);
        rowsc = (r < M) ? g_scale[r] : 0.f;
    }

    auto load_tile = [&](int k0, int buf) {
        if (TRANSA) {
#pragma unroll
            for (int it = 0; it < 2; it++) {
                int item = it * 128 + tid;
                int kk = item >> 4;
                int r4 = (item & 15) * 4;
                float4 v = make_float4(0.f, 0.f, 0.f, 0.f);
                int row = rowBase + r4;
                if (row < M) {
                    v = *(const float4*)&A[(long)(k0 + kk) * lda + row];
                    if (A2) {
                        float4 w = *(const float4*)&A2[(long)(k0 + kk) * lda + row];
                        v.x += w.x; v.y += w.y; v.z += w.z; v.w += w.w;
                    }
                }
                As[buf][r4 + 0][kk] = f2tf32(v.x);
                As[buf][r4 + 1][kk] = f2tf32(v.y);
                As[buf][r4 + 2][kk] = f2tf32(v.z);
                As[buf][r4 + 3][kk] = f2tf32(v.w);
            }
        } else {
            int lr = tid >> 1;
            int lc = (tid & 1) * 8;
            int r = rowBase + lr;
            float4 a0 = make_float4(0.f, 0.f, 0.f, 0.f);
            float4 a1 = make_float4(0.f, 0.f, 0.f, 0.f);
            if (r < M) {
                a0 = *(const float4*)&A[(long)r * lda + k0 + lc];
                a1 = *(const float4*)&A[(long)r * lda + k0 + lc + 4];
                if (A2) {
                    float4 w0 = *(const float4*)&A2[(long)r * lda + k0 + lc];
                    float4 w1 = *(const float4*)&A2[(long)r * lda + k0 + lc + 4];
                    a0.x += w0.x; a0.y += w0.y; a0.z += w0.z; a0.w += w0.w;
                    a1.x += w1.x; a1.y += w1.y; a1.z += w1.z; a1.w += w1.w;
                }
            }
            if (ANORM) {
                float4 n0 = *(const float4*)&nw[k0 + lc];
                float4 n1 = *(const float4*)&nw[k0 + lc + 4];
                a0.x *= rowsc * n0.x; a0.y *= rowsc * n0.y;
                a0.z *= rowsc * n0.z; a0.w *= rowsc * n0.w;
                a1.x *= rowsc * n1.x; a1.y *= rowsc * n1.y;
                a1.z *= rowsc * n1.z; a1.w *= rowsc * n1.w;
            }
            As[buf][lr][lc + 0] = f2tf32(a0.x); As[buf][lr][lc + 1] = f2tf32(a0.y);
            As[buf][lr][lc + 2] = f2tf32(a0.z); As[buf][lr][lc + 3] = f2tf32(a0.w);
            As[buf][lr][lc + 4] = f2tf32(a1.x); As[buf][lr][lc + 5] = f2tf32(a1.y);
            As[buf][lr][lc + 6] = f2tf32(a1.z); As[buf][lr][lc + 7] = f2tf32(a1.w);
        }
        {
            int lr = tid >> 1;
            int lc = (tid & 1) * 8;
            int col = colBase + lr;
            float4 b0 = make_float4(0.f, 0.f, 0.f, 0.f);
            float4 b1 = make_float4(0.f, 0.f, 0.f, 0.f);
            if (col < N) {
                b0 = *(const float4*)&W[(long)col * K + k0 + lc];
                b1 = *(const float4*)&W[(long)col * K + k0 + lc + 4];
            }
            Bs[buf][lr][lc + 0] = f2tf32(b0.x); Bs[buf][lr][lc + 1] = f2tf32(b0.y);
            Bs[buf][lr][lc + 2] = f2tf32(b0.z); Bs[buf][lr][lc + 3] = f2tf32(b0.w);
            Bs[buf][lr][lc + 4] = f2tf32(b1.x); Bs[buf][lr][lc + 5] = f2tf32(b1.y);
            Bs[buf][lr][lc + 6] = f2tf32(b1.z); Bs[buf][lr][lc + 7] = f2tf32(b1.w);
        }
    };

    float acc[2][4][4];
#pragma unroll
    for (int mi = 0; mi < 2; mi++)
#pragma unroll
        for (int ni = 0; ni < 4; ni++)
#pragma unroll
            for (int u = 0; u < 4; u++) acc[mi][ni][u] = 0.f;

    load_tile(kbase, 0);
    __syncthreads();

    for (int c = 0; c < nk; c++) {
        int cur = c & 1, nxt = cur ^ 1;
        if (c + 1 < nk) load_tile(kbase + (c + 1) * TBK, nxt);
#pragma unroll
        for (int c2 = 0; c2 < 2; c2++) {
            uint32_t af[2][4], bf[4][2];
#pragma unroll
            for (int mi = 0; mi < 2; mi++) {
                int r = wm * 32 + mi * 16 + qr;
                af[mi][0] = As[cur][r][c2 * 8 + qc];
                af[mi][1] = As[cur][r + 8][c2 * 8 + qc];
                af[mi][2] = As[cur][r][c2 * 8 + 4 + qc];
                af[mi][3] = As[cur][r + 8][c2 * 8 + 4 + qc];
            }
#pragma unroll
            for (int ni = 0; ni < 4; ni++) {
                int n = wn * 32 + ni * 8 + qr;
                bf[ni][0] = Bs[cur][n][c2 * 8 + qc];
                bf[ni][1] = Bs[cur][n][c2 * 8 + 4 + qc];
            }
#pragma unroll
            for (int mi = 0; mi < 2; mi++)
#pragma unroll
                for (int ni = 0; ni < 4; ni++)
                    mma_tf32(acc[mi][ni], af[mi], bf[ni]);
        }
        __syncthreads();
    }

    if (TRANSC) {
        __shared__ float stage[TBN][68];
#pragma unroll
        for (int mi = 0; mi < 2; mi++) {
#pragma unroll
            for (int ni = 0; ni < 4; ni++) {
                int r0 = wm * 32 + mi * 16 + qr;
                int c0 = wn * 32 + ni * 8 + 2 * qc;
#pragma unroll
                for (int u = 0; u < 4; u++) {
                    int rl = r0 + (u >= 2 ? 8 : 0);
                    int cl = c0 + (u & 1);
                    float v = acc[mi][ni][u];
                    if (EPI == 1) v = softplusf(v + bias[colBase + cl]);
                    stage[cl][rl] = v;
                }
            }
        }
        __syncthreads();
#pragma unroll
        for (int it = 0; it < 8; it++) {
            int item = it * 128 + tid;
            int col = item >> 4;
            int r = (item & 15) * 4;
            int row = rowBase + r;
            if (row < M) {
                float4 v = *(const float4*)&stage[col][r];
                *(float4*)&C[(long)(colBase + col) * ldc + row] = v;
            }
        }
    } else {
#pragma unroll
        for (int mi = 0; mi < 2; mi++) {
#pragma unroll
            for (int ni = 0; ni < 4; ni++) {
                int r0 = rowBase + wm * 32 + mi * 16 + qr;
                int c0 = colBase + wn * 32 + ni * 8 + 2 * qc;
#pragma unroll
                for (int u = 0; u < 4; u++) {
                    int row = r0 + (u >= 2 ? 8 : 0);
                    int col = c0 + (u & 1);
                    if (row >= M || col >= N) continue;
                    float v = acc[mi][ni][u];
                    if (EPI == 1) {
                        v = softplusf(v + bias[col]);
                    } else if (EPI == 2) {
                        if (ks == 0) {
                            int tl = row % LSEQ;
                            int t = tl / NPATCH, p = tl % NPATCH;
                            v += bias[col] + pos[p * DM + col] + temp[t * DM + col];
                        }
                    }
                    if (ATOMIC) atomicAdd(&C[(long)row * ldc + col], v);
                    else        C[(long)row * ldc + col] = v;
                }
            }
        }
    }
}

// ---------------- slim residual add + rms scale + zero g_xz -------------------
__global__ void __launch_bounds__(128)
addnorm_kernel(int first) {
    int wid = threadIdx.x >> 5, lane = threadIdx.x & 31;
    int n = blockIdx.x * 4 + wid;
    {
        int gt = blockIdx.x * 128 + threadIdx.x;
        float4* xzp = (float4*)g_xz;
        float4 zero = make_float4(0.f, 0.f, 0.f, 0.f);
#pragma unroll
        for (int i = 0; i < 8; i++) xzp[(long)i * 50176 + gt] = zero;
    }

    const float4* hp = (const float4*)(g_hidden + (long)n * DM);
    float4* rp = (float4*)(g_resid + (long)n * DM);
    float4 h0 = hp[lane], h1 = hp[32 + lane];
    if (!first) {
        float4 r0 = rp[lane], r1 = rp[32 + lane];
        h0.x += r0.x; h0.y += r0.y; h0.z += r0.z; h0.w += r0.w;
        h1.x += r1.x; h1.y += r1.y; h1.z += r1.z; h1.w += r1.w;
    }
    rp[lane] = h0; rp[32 + lane] = h1;
    float ss = h0.x*h0.x + h0.y*h0.y + h0.z*h0.z + h0.w*h0.w
             + h1.x*h1.x + h1.y*h1.y + h1.z*h1.z + h1.w*h1.w;
#pragma unroll
    for (int m = 16; m; m >>= 1) ss += __shfl_xor_sync(0xffffffffu, ss, m);
    if (lane == 0) g_scale[n] = rsqrtf(ss / (float)DM + 1e-5f);
}

// ---------------- conv + silu + transpose  (and z-gate transpose) -------------
#define CT 64
#define CD 32
__global__ void __launch_bounds__(256)
conv_kernel(const float* __restrict__ cwf, const float* __restrict__ cbf,
            const float* __restrict__ cwb, const float* __restrict__ cbb) {
    {
        int bid = (blockIdx.z * gridDim.y + blockIdx.y) * gridDim.x + blockIdx.x;
        int gid = bid * 256 + threadIdx.x;
        const int NH4 = NT * DM / 4;          // 100352
        const int ND4 = 2 * NT * 48 / 4;      // 37632
        if (gid < NH4) ((float4*)g_hidden)[gid] = make_float4(0.f, 0.f, 0.f, 0.f);
        else if (gid < NH4 + ND4) ((float4*)g_dbl)[gid - NH4] = make_float4(0.f, 0.f, 0.f, 0.f);
    }
    __shared__ float tile[CT + 3][CD + 1];
    int mode = blockIdx.z / BB;
    int b = blockIdx.z % BB;
    int t0 = blockIdx.x * CT;
    int d0 = blockIdx.y * CD;
    int tid = threadIdx.x;
    int colbase = (mode == 2 ? DI : 0) + d0;

    int rr = tid >> 3, cc = (tid & 7) * 4;
#pragma unroll
    for (int it = 0; it < 3; it++) {
        int r = it * 32 + rr;
        if (r < CT + 3) {
            int ss = t0 - 3 + r;
            float4 v = make_float4(0.f, 0.f, 0.f, 0.f);
            if (ss >= 0 && ss < LSEQ) {
                int src = (mode == 1) ? (LSEQ - 1 - ss) : ss;
                v = *(const float4*)&g_xz[(long)(b * LSEQ + src) * (2 * DI) + colbase + cc];
            }
            tile[r][cc + 0] = v.x; tile[r][cc + 1] = v.y;
            tile[r][cc + 2] = v.z; tile[r][cc + 3] = v.w;
        }
    }
    __syncthreads();

    int tl = tid & 63, dg = tid >> 6;
    int tt = t0 + tl;
    if (tt >= LSEQ) return;
    if (mode == 2) {
#pragma unroll
        for (int i = 0; i < 8; i++) {
            int dl = dg * 8 + i;
            float v = siluf(tile[tl + 3][dl]);
            g_gz[(long)(d0 + dl) * NT + b * LSEQ + tt] = v;
        }
    } else {
        const float* cw = mode ? cwb : cwf;
        const float* cb = mode ? cbb : cbf;
#pragma unroll
        for (int i = 0; i < 8; i++) {
            int dl = dg * 8 + i;
            int d = d0 + dl;
            float acc = cb[d];
#pragma unroll
            for (int k = 0; k < 4; k++)
                acc = fmaf(tile[tl + k][dl], cw[d * 4 + k], acc);
            g_xs[((long)mode * DI + d) * NT + b * LSEQ + tt] = siluf(acc);
        }
    }
}

// ---------------- chunked SSM scan (two-pass, transposed inputs) --------------
// pass1 launched for chunks 0..NCHUNK-2 only (last chunk's summary is unused).
__global__ void scan_pass1_kernel(int layer) {
    int dir = blockIdx.z;
    int c = blockIdx.y;
    int tid = threadIdx.x;
    int grp = tid >> 4, s = tid & 15;
    int ch = blockIdx.x * 16 + grp;
    int b = ch >> 9, d = ch & (DI - 1);
    int e = ((dir * BB + b) * DI + d) * DSTATE + s;

    const float A_ds = g_A[(dir * NDEPTH + layer) * DI * DSTATE + d * DSTATE + s];
    long base = ((long)dir * DI + d) * NT + b * LSEQ;
    const float* dtp = g_dt + base;
    const float* xsp = g_xs + base;
    const float* dblp = g_dbl + ((long)dir * NT + b * LSEQ) * 48;

    float P = 1.f, q = 0.f;
    int t0 = c * CLEN;
    for (int tb = 0; tb < CLEN; tb += 16) {
        int tt = t0 + tb;
        float dtv = dtp[tt + s];
        float uv  = xsp[tt + s];
#pragma unroll
        for (int j = 0; j < 16; j++) {
            float dt = __shfl_sync(0xffffffffu, dtv, j, 16);
            float u  = __shfl_sync(0xffffffffu, uv,  j, 16);
            float Bv = dblp[(tt + j) * 48 + 16 + s];
            float a = __expf(dt * A_ds);
            P *= a;
            q = fmaf(a, q, (dt * u) * Bv);
        }
    }
    g_P[c][e] = P;
    g_q[c][e] = q;
}

__global__ void scan_pass2_kernel(int layer, const float* __restrict__ Dsf,
                                  const float* __restrict__ Dsb) {
    int dir = blockIdx.z;
    int c = blockIdx.y;
    int tid = threadIdx.x;
    int grp = tid >> 4, s = tid & 15;
    int ch = blockIdx.x * 16 + grp;
    int b = ch >> 9, d = ch & (DI - 1);
    int e = ((dir * BB + b) * DI + d) * DSTATE + s;

    const float A_ds = g_A[(dir * NDEPTH + layer) * DI * DSTATE + d * DSTATE + s];
    const float Dd = (dir ? Dsb : Dsf)[d];
    long base = ((long)dir * DI + d) * NT + b * LSEQ;
    const float* dtp = g_dt + base;
    const float* xsp = g_xs + base;
    const float* dblp = g_dbl + ((long)dir * NT + b * LSEQ) * 48;
    const float* gzp = g_gz + (long)d * NT + b * LSEQ;
    float* yp = g_y + base;

    float h = 0.f;
    for (int cc = 0; cc < c; cc++) h = fmaf(g_P[cc][e], h, g_q[cc][e]);

    int t0 = c * CLEN;
    float yb0 = 0.f, yb1 = 0.f, yb2 = 0.f;
    for (int tb = 0; tb < CLEN; tb += 16) {
        int tt = t0 + tb;
        float dtv = dtp[tt + s];
        float uv  = xsp[tt + s];
#pragma unroll
        for (int j = 0; j < 16; j++) {
            int ss = tt + j;
            float dt = __shfl_sync(0xffffffffu, dtv, j, 16);
            float u  = __shfl_sync(0xffffffffu, uv,  j, 16);
            float Bv = dblp[ss * 48 + 16 + s];
            float Cv = dblp[ss * 48 + 32 + s];
            float a = __expf(dt * A_ds);
            h = fmaf(a, h, (dt * u) * Bv);
            float p = h * Cv;
            p += __shfl_xor_sync(0xffffffffu, p, 8);
            p += __shfl_xor_sync(0xffffffffu, p, 4);
            p += __shfl_xor_sync(0xffffffffu, p, 2);
            p += __shfl_xor_sync(0xffffffffu, p, 1);
            if (s == 0) {
                int orig = dir ? (LSEQ - 1 - ss) : ss;
                float val = (p + Dd * u) * gzp[orig];
                if ((j & 3) == 0) yb0 = val;
                else if ((j & 3) == 1) yb1 = val;
                else if ((j & 3) == 2) yb2 = val;
                else {
                    float4 o = dir ? make_float4(val, yb2, yb1, yb0)
                                   : make_float4(yb0, yb1, yb2, val);
                    int addr = dir ? (LSEQ - 1 - ss) : (ss - 3);
                    *(float4*)&yp[addr] = o;
                }
            }
        }
    }
}

// ---------------- heads (with fused final rmsnorm) ----------------------------
__global__ void heads_kernel(const float* __restrict__ normf_w,
                             const float* __restrict__ bw1, const float* __restrict__ bb1,
                             const float* __restrict__ bw2, const float* __restrict__ bb2,
                             const float* __restrict__ pw1, const float* __restrict__ pb1,
                             const float* __restrict__ pw2, const float* __restrict__ pb2,
                             float* __restrict__ out) {
    int h = blockIdx.x;
    int b = blockIdx.y;
    int tid = threadIdx.x;
    __shared__ float sin_[DM];
    __shared__ float hidv[DM];
    __shared__ float sw[8];

    int n = b * LSEQ + h;
    float r = g_resid[n * DM + tid] + g_hidden[n * DM + tid];
    float ss = r * r;
#pragma unroll
    for (int m = 16; m; m >>= 1) ss += __shfl_xor_sync(0xffffffffu, ss, m);
    if ((tid & 31) == 0) sw[tid >> 5] = ss;
    __syncthreads();
    float tot = 0.f;
#pragma unroll
    for (int i = 0; i < 8; i++) tot += sw[i];
    float sc = rsqrtf(tot / (float)DM + 1e-5f);
    sin_[tid] = r * sc * normf_w[tid];
    __syncthreads();

    const float *w1, *b1, *w2, *b2;
    int nout; bool sig;
    if (h == 0) { w1 = bw1; b1 = bb1; w2 = bw2; b2 = bb2; nout = 3; sig = false; }
    else {
        int i = h - 1;
        w1 = pw1 + (long)i * DM * DM; b1 = pb1 + i * DM;
        w2 = pw2 + i * 2 * DM;        b2 = pb2 + i * 2;
        nout = 2; sig = true;
    }
    float acc = b1[tid];
    for (int k = 0; k < DM; k++) acc = fmaf(sin_[k], w1[(long)tid * DM + k], acc);
    hidv[tid] = fmaxf(acc, 0.f);
    __syncthreads();

    int w = tid >> 5, lane = tid & 31;
    if (w < nout) {
        float a = 0.f;
        for (int k = lane; k < DM; k += 32) a += hidv[k] * w2[w * DM + k];
#pragma unroll
        for (int m = 16; m; m >>= 1) a += __shfl_xor_sync(0xffffffffu, a, m);
        if (lane == 0) {
            float v = a + b2[w];
            if (sig) v = 1.f / (1.f + __expf(-v));
            int o = (h == 0) ? (b * 11 + w) : (b * 11 + 3 + (h - 1) * 2 + w);
            out[o] = v;
        }
    }
}

// ---------------- host side ----------------
extern "C" void kernel_launch(void* const* d_in, const int* in_sizes, int n_in,
                              void* d_out, int out_size) {
    (void)in_sizes; (void)n_in; (void)out_size;
    const float* x        = (const float*)d_in[0];
    const float* patch_w  = (const float*)d_in[1];
    const float* patch_b  = (const float*)d_in[2];
    const float* pos      = (const float*)d_in[3];
    const float* temp     = (const float*)d_in[4];
    const float* in_proj  = (const float*)d_in[5];
    const float* convf_w  = (const float*)d_in[6];
    const float* convf_b  = (const float*)d_in[7];
    const float* xprojf   = (const float*)d_in[8];
    const float* dtf_w    = (const float*)d_in[9];
    const float* dtf_b    = (const float*)d_in[10];
    const float* A_logf   = (const float*)d_in[11];
    const float* Dsf      = (const float*)d_in[12];
    const float* convb_w  = (const float*)d_in[13];
    const float* convb_b  = (const float*)d_in[14];
    const float* xprojb   = (const float*)d_in[15];
    const float* dtb_w    = (const float*)d_in[16];
    const float* dtb_b    = (const float*)d_in[17];
    const float* A_logb   = (const float*)d_in[18];
    const float* Dsb      = (const float*)d_in[19];
    const float* out_proj = (const float*)d_in[20];
    const float* norm_w   = (const float*)d_in[21];
    const float* normf_w  = (const float*)d_in[22];
    const float* bbox_w1  = (const float*)d_in[23];
    const float* bbox_b1  = (const float*)d_in[24];
    const float* bbox_w2  = (const float*)d_in[25];
    const float* bbox_b2  = (const float*)d_in[26];
    const float* pix_w1   = (const float*)d_in[27];
    const float* pix_b1   = (const float*)d_in[28];
    const float* pix_w2   = (const float*)d_in[29];
    const float* pix_b2   = (const float*)d_in[30];
    float* out = (float*)d_out;

    float *p_im2col, *p_hidden, *p_resid, *p_xz, *p_xs, *p_dbl, *p_dt, *p_y;
    cudaGetSymbolAddress((void**)&p_im2col, g_im2col);
    cudaGetSymbolAddress((void**)&p_hidden, g_hidden);
    cudaGetSymbolAddress((void**)&p_resid,  g_resid);
    cudaGetSymbolAddress((void**)&p_xz,     g_xz);
    cudaGetSymbolAddress((void**)&p_xs,     g_xs);
    cudaGetSymbolAddress((void**)&p_dbl,    g_dbl);
    cudaGetSymbolAddress((void**)&p_dt,     g_dt);
    cudaGetSymbolAddress((void**)&p_y,      g_y);

    const int GY = (NT + TBM - 1) / TBM;   // 25

    im2col_kernel<<<(NT * KPATCH + 255) / 256, 256>>>(x, A_logf, A_logb);

    // patch embed: N=256, K=768, split-K 8, atomic, EPI=2 -> 800 blocks
    mma_gemm_kernel<2, true, false, false, false><<<dim3(4, GY, 8), 128>>>(
        p_im2col, nullptr, KPATCH, patch_w, nullptr, p_hidden, DM,
        NT, DM, KPATCH, 8, patch_b, nullptr, pos, temp, 0, 0, nullptr);

    for (int i = 0; i < NDEPTH; i++) {
        addnorm_kernel<<<NT / 4, 128>>>(i == 0);
        // in_proj: ANORM, N=1024, K=256, split-K 2, atomic -> 800 blocks
        mma_gemm_kernel<0, true, false, false, true><<<dim3(16, GY, 2), 128>>>(
            p_resid, nullptr, DM, in_proj + (long)i * 2 * DI * DM, nullptr,
            p_xz, 2 * DI, NT, 2 * DI, DM, 2, nullptr, nullptr, nullptr, nullptr, 0, 0,
            norm_w + i * DM);
        // conv + silu + transpose (fwd, bwd, z-gate); zeroes hidden & dbl
        conv_kernel<<<dim3((LSEQ + CT - 1) / CT, DI / CD, 3 * BB), 256>>>(
            convf_w + (long)i * DI * 4, convf_b + i * DI,
            convb_w + (long)i * DI * 4, convb_b + i * DI);
        // xproj: TRANSA, N=48, K=512, dirs 2, split-K 16, atomic -> 800 blocks
        mma_gemm_kernel<0, true, true, false, false><<<dim3(1, GY, 32), 128>>>(
            p_xs, nullptr, NT, xprojf + (long)i * 48 * DI, xprojb + (long)i * 48 * DI,
            p_dbl, 48, NT, 48, DI, 16, nullptr, nullptr, nullptr, nullptr,
            (long)DI * NT, (long)NT * 48, nullptr);
        // dt: N=512, K=16, dirs 2, softplus, TRANSC -> dt_T (400 blocks)
        mma_gemm_kernel<1, false, false, true, false><<<dim3(8, GY, 2), 128>>>(
            p_dbl, nullptr, 48, dtf_w + (long)i * DI * DTR, dtb_w + (long)i * DI * DTR,
            p_dt, NT, NT, DI, DTR, 1, dtf_b + i * DI, dtb_b + i * DI, nullptr, nullptr,
            (long)NT * 48, (long)DI * NT, nullptr);
        // pass1 skips last chunk (summary unused)
        scan_pass1_kernel<<<dim3(64, NCHUNK - 1, 2), 256>>>(i);
        scan_pass2_kernel<<<dim3(64, NCHUNK, 2), 256>>>(i, Dsf + i * DI, Dsb + i * DI);
        // out_proj: TRANSA, N=256, K=512, split-K 8, atomic -> 800 blocks
        mma_gemm_kernel<0, true, true, false, false><<<dim3(4, GY, 8), 128>>>(
            p_y, p_y + (long)DI * NT, NT, out_proj + (long)i * DM * DI, nullptr,
            p_hidden, DM, NT, DM, DI, 8, nullptr, nullptr, nullptr, nullptr, 0, 0, nullptr);
    }

    heads_kernel<<<dim3(5, BB), 256>>>(normf_w, bbox_w1, bbox_b1, bbox_w2, bbox_b2,
                                       pix_w1, pix_b1, pix_w2, pix_b2, out);
}